// round 1
// baseline (speedup 1.0000x reference)
#include <cuda_runtime.h>
#include <cuda_bf16.h>
#include <cstdint>

// Problem dims
#define BB   256
#define VV   50
#define NNODE 32
#define DD   128
#define NDI  4096
#define HH   384
#define LL   12
#define CSS  10
#define GG   1560
#define HSS  64
#define OUTT 128

// ---------------- scratch (static device globals; no allocation) ----------------
__device__ float g_Wk[(size_t)GG * NDI];        // kernel_w[:, :4096] padded (stride 4096)
__device__ float g_WsumT[GG];                   // kernel_w[:,4096] + rec_w[:,384]
__device__ float g_Wr[(size_t)GG * HH];         // rec_w[:, :384]
__device__ float g_XO[(size_t)VV * BB * GG];    // [v][b][g]  precomputed input part (+biases+time)
__device__ float g_xobuf[BB * GG];              // current step xo
__device__ float g_h[BB * HH];
__device__ float g_c[BB * HH];
__device__ float g_hs[(size_t)VV * BB * HH];    // [t][b][h]
__device__ float g_dists[VV * BB];              // [t][b]
__device__ float g_ld[VV * BB * CSS];           // [t][b][k]
__device__ float g_A[(size_t)VV * BB * HH * CSS];   // [t][b][k*384+h] = hs*ld
__device__ float g_mh[(size_t)VV * BB * HH];
__device__ float g_hid[(size_t)VV * BB * HSS];
__device__ float g_theme[(size_t)VV * BB * HH];
__device__ float g_convT[(size_t)HH * HH * CSS];    // [o][k][h]
__device__ float g_rnn[(size_t)BB * VV * HH];       // [b][v][h]
__device__ float g_outPart[16 * BB * OUTT];

__device__ __forceinline__ float sigmoidf(float x) { return 1.f / (1.f + expf(-x)); }

// ---------------- prep: pad weights, transpose conv_w, zero state ----------------
__global__ void k_prep(const float* __restrict__ kw, const float* __restrict__ rw,
                       const float* __restrict__ cw)
{
    const long NWK = (long)GG * NDI;          // 6,389,760
    const long NWR = (long)GG * HH;           // 599,040
    const long NCT = (long)HH * HH * CSS;     // 1,474,560
    const long NZ  = 2L * BB * HH;            // 196,608
    long idx = (long)blockIdx.x * 256 + threadIdx.x;
    if (idx < NWK) {
        long g = idx / NDI, k = idx % NDI;
        g_Wk[idx] = kw[g * 4097 + k];
        return;
    }
    idx -= NWK;
    if (idx < NWR) {
        long g = idx / HH, j = idx % HH;
        g_Wr[idx] = rw[g * 385 + j];
        return;
    }
    idx -= NWR;
    if (idx < GG) {
        g_WsumT[idx] = kw[idx * 4097 + 4096] + rw[idx * 385 + 384];
        return;
    }
    idx -= GG;
    if (idx < NCT) {
        long o = idx / (HH * CSS);
        long c = idx % (HH * CSS);
        long k = c / HH, h = c % HH;
        g_convT[idx] = cw[(o * HH + h) * CSS + k];
        return;
    }
    idx -= NCT;
    if (idx < NZ) {
        if (idx < BB * HH) g_h[idx] = 0.f; else g_c[idx - BB * HH] = 0.f;
    }
}

// ---------------- big GEMM: XO[v][b][g] = x[bv] . Wk[g] + kb+rb + time*(WkT+WrT) ----
// fused embedding gather in A-tile load. M=12800 (bv), N=1560 (g), K=4096.
__global__ __launch_bounds__(256, 2) void k_gemm_xo(const int* __restrict__ ids,
    const float* __restrict__ embed, const float* __restrict__ kb,
    const float* __restrict__ rb, const float* __restrict__ tv)
{
    __shared__ float As[16][128];
    __shared__ float Bs[16][128];
    int tid = threadIdx.x;
    int bn = blockIdx.x, bm = blockIdx.y;
    int lrow = tid >> 2;             // 0..63
    int lcol = (tid & 3) << 2;       // 0,4,8,12
    int trow = tid >> 4, tcol = tid & 15;
    int m0 = bm * 128, g0 = bn * 128;
    float acc[8][8] = {};

    for (int k0 = 0; k0 < NDI; k0 += 16) {
#pragma unroll
        for (int r = 0; r < 128; r += 64) {
            int m = m0 + lrow + r;
            int kk = k0 + lcol;
            int id = ids[m * NNODE + (kk >> 7)];
            float4 a4 = *reinterpret_cast<const float4*>(embed + (size_t)id * DD + (kk & 127));
            As[lcol + 0][lrow + r] = a4.x;
            As[lcol + 1][lrow + r] = a4.y;
            As[lcol + 2][lrow + r] = a4.z;
            As[lcol + 3][lrow + r] = a4.w;
            int g = g0 + lrow + r;
            float4 b4 = make_float4(0.f, 0.f, 0.f, 0.f);
            if (g < GG)
                b4 = *reinterpret_cast<const float4*>(g_Wk + (size_t)g * NDI + k0 + lcol);
            Bs[lcol + 0][lrow + r] = b4.x;
            Bs[lcol + 1][lrow + r] = b4.y;
            Bs[lcol + 2][lrow + r] = b4.z;
            Bs[lcol + 3][lrow + r] = b4.w;
        }
        __syncthreads();
#pragma unroll
        for (int p = 0; p < 16; p++) {
            float ar[8], br[8];
#pragma unroll
            for (int i = 0; i < 8; i++) ar[i] = As[p][trow * 8 + i];
#pragma unroll
            for (int j = 0; j < 8; j++) br[j] = Bs[p][tcol * 8 + j];
#pragma unroll
            for (int i = 0; i < 8; i++)
#pragma unroll
                for (int j = 0; j < 8; j++)
                    acc[i][j] = fmaf(ar[i], br[j], acc[i][j]);
        }
        __syncthreads();
    }
#pragma unroll
    for (int i = 0; i < 8; i++) {
        int m = m0 + trow * 8 + i;          // m = b*50 + v
        int b = m / VV, v = m % VV;
        float tval = tv[m];                 // time[b][v]
#pragma unroll
        for (int j = 0; j < 8; j++) {
            int g = g0 + tcol * 8 + j;
            if (g < GG)
                g_XO[((size_t)v * BB + b) * GG + g] =
                    acc[i][j] + kb[g] + rb[g] + tval * g_WsumT[g];
        }
    }
}

// ---------------- generic 64x64 NT tile: C = A(64xK) * B(64xK)^T, 256 thr, TM=TN=4 ----
__device__ __forceinline__ void gemm64(const float* __restrict__ A, int lda,
                                       const float* __restrict__ Bm, int ldb,
                                       int K, int brows, float (&acc)[4][4],
                                       float* As, float* Bs)
{
    int tid = threadIdx.x;
    int lrow = tid >> 2;
    int lcol = (tid & 3) << 2;
    int trow = tid >> 4;
    int tcol = tid & 15;
    for (int k0 = 0; k0 < K; k0 += 16) {
        float4 a4 = *reinterpret_cast<const float4*>(A + (size_t)lrow * lda + k0 + lcol);
        float4 b4 = make_float4(0.f, 0.f, 0.f, 0.f);
        if (lrow < brows)
            b4 = *reinterpret_cast<const float4*>(Bm + (size_t)lrow * ldb + k0 + lcol);
        As[(lcol + 0) * 64 + lrow] = a4.x;
        As[(lcol + 1) * 64 + lrow] = a4.y;
        As[(lcol + 2) * 64 + lrow] = a4.z;
        As[(lcol + 3) * 64 + lrow] = a4.w;
        Bs[(lcol + 0) * 64 + lrow] = b4.x;
        Bs[(lcol + 1) * 64 + lrow] = b4.y;
        Bs[(lcol + 2) * 64 + lrow] = b4.z;
        Bs[(lcol + 3) * 64 + lrow] = b4.w;
        __syncthreads();
#pragma unroll
        for (int p = 0; p < 16; p++) {
            float ar[4], br[4];
#pragma unroll
            for (int i = 0; i < 4; i++) ar[i] = As[p * 64 + trow * 4 + i];
#pragma unroll
            for (int j = 0; j < 4; j++) br[j] = Bs[p * 64 + tcol * 4 + j];
#pragma unroll
            for (int i = 0; i < 4; i++)
#pragma unroll
                for (int j = 0; j < 4; j++)
                    acc[i][j] = fmaf(ar[i], br[j], acc[i][j]);
        }
        __syncthreads();
    }
}

// ---------------- per-step: xo = XO[t] + h @ Wr^T ----------------
__global__ __launch_bounds__(256) void k_rec(int t)
{
    __shared__ float As[16 * 64];
    __shared__ float Bs[16 * 64];
    int g0 = blockIdx.x * 64;
    int b0 = blockIdx.y * 64;
    float acc[4][4] = {};
    int brows = GG - g0; if (brows > 64) brows = 64;
    gemm64(g_h + (size_t)b0 * HH, HH, g_Wr + (size_t)g0 * HH, HH, HH, brows, acc, As, Bs);
    int trow = threadIdx.x >> 4, tcol = threadIdx.x & 15;
#pragma unroll
    for (int i = 0; i < 4; i++) {
        int b = b0 + trow * 4 + i;
#pragma unroll
        for (int j = 0; j < 4; j++) {
            int g = g0 + tcol * 4 + j;
            if (g < GG)
                g_xobuf[b * GG + g] = acc[i][j] + g_XO[((size_t)t * BB + b) * GG + g];
        }
    }
}

// ---------------- per-step: gates + cell update ----------------
__global__ void k_gates(int t)
{
    int b = blockIdx.x;
    int tid = threadIdx.x;   // 128
    __shared__ float sfm[LL], sim[LL];
    const float* xo = g_xobuf + b * GG;
    if (tid == 0) {
        float v[LL], mx = -1e30f;
#pragma unroll
        for (int i = 0; i < LL; i++) { v[i] = xo[i]; mx = fmaxf(mx, v[i]); }
        float s = 0.f;
#pragma unroll
        for (int i = 0; i < LL; i++) { v[i] = expf(v[i] - mx); s += v[i]; }
        float inv = 1.f / s, run = 0.f, fsum = 0.f;
#pragma unroll
        for (int i = 0; i < LL; i++) { run += v[i] * inv; sfm[i] = run; fsum += run; }
        g_dists[t * BB + b] = 1.f - fsum / (float)LL;
    } else if (tid == 32) {
        float v[LL], mx = -1e30f;
#pragma unroll
        for (int i = 0; i < LL; i++) { v[i] = xo[LL + i]; mx = fmaxf(mx, v[i]); }
        float s = 0.f;
#pragma unroll
        for (int i = 0; i < LL; i++) { v[i] = expf(v[i] - mx); s += v[i]; }
        float inv = 1.f / s, run = 0.f;
#pragma unroll
        for (int i = LL - 1; i >= 0; i--) { run += v[i] * inv; sim[i] = run; }
    }
    __syncthreads();
#pragma unroll
    for (int r = 0; r < 3; r++) {
        int hh = tid + r * 128;
        int l = hh >> 5;
        float fg = sigmoidf(xo[24 + hh]);
        float ig = sigmoidf(xo[24 + 384 + hh]);
        float og = sigmoidf(xo[24 + 768 + hh]);
        float ci = tanhf(xo[24 + 1152 + hh]);
        float fmv = sfm[l], imv = sim[l], ov = fmv * imv;
        float c = g_c[b * HH + hh];
        float cn = ov * (fg * c + ig * ci) + (fmv - ov) * c + (imv - ov) * ci;
        float hv = og * tanhf(cn);
        g_c[b * HH + hh] = cn;
        g_h[b * HH + hh] = hv;
        g_hs[((size_t)t * BB + b) * HH + hh] = hv;
    }
}

// ---------------- post: ld[t][b][k] = softmax_k(cumsum(tmp_dis)) ----------------
__global__ void k_ld()
{
    int idx = blockIdx.x * 256 + threadIdx.x;   // < 12800
    int t = idx / BB, b = idx % BB;
    float cum[CSS], run = 0.f;
#pragma unroll
    for (int k = 0; k < CSS; k++) {
        int s = t - (CSS - 1) + k;
        float d = (s >= 0) ? g_dists[s * BB + b] : 0.f;
        run += d;
        cum[k] = run;
    }
    float mx = cum[0];
#pragma unroll
    for (int k = 1; k < CSS; k++) mx = fmaxf(mx, cum[k]);
    float e[CSS], s = 0.f;
#pragma unroll
    for (int k = 0; k < CSS; k++) { e[k] = expf(cum[k] - mx); s += e[k]; }
    float inv = 1.f / s;
#pragma unroll
    for (int k = 0; k < CSS; k++) g_ld[(size_t)idx * CSS + k] = e[k] * inv;
}

// ---------------- post: A[t][b][k*384+h] = hs[t-9+k][b][h] * ld[t][b][k] ----------------
__global__ void k_abuild()
{
    long idx = (long)blockIdx.x * 256 + threadIdx.x;   // < 49,152,000
    int t = (int)(idx / (BB * HH * CSS));
    int r = (int)(idx % (BB * HH * CSS));
    int b = r / (HH * CSS);
    int c = r % (HH * CSS);
    int k = c / HH, h = c % HH;
    int s = t - (CSS - 1) + k;
    float v = 0.f;
    if (s >= 0)
        v = g_hs[((size_t)s * BB + b) * HH + h] * g_ld[((size_t)t * BB + b) * CSS + k];
    g_A[idx] = v;
}

// ---------------- post: mh = mean_k lh ----------------
__global__ void k_mh()
{
    long idx = (long)blockIdx.x * 256 + threadIdx.x;   // < 4,915,200
    int t = (int)(idx / (BB * HH));
    int r = (int)(idx % (BB * HH));
    int b = r / HH, h = r % HH;
    float s = 0.f;
    size_t base = (size_t)t * (BB * HH * CSS) + (size_t)b * (HH * CSS) + h;
#pragma unroll
    for (int k = 0; k < CSS; k++) s += g_A[base + (size_t)k * HH];
    g_mh[idx] = s * 0.1f;
}

// ---------------- theme MLP (two small GEMMs) ----------------
__global__ __launch_bounds__(256) void k_theme1(const float* __restrict__ sw,
                                                const float* __restrict__ sb)
{
    __shared__ float As[16 * 64];
    __shared__ float Bs[16 * 64];
    int m0 = blockIdx.y * 64;
    float acc[4][4] = {};
    gemm64(g_mh + (size_t)m0 * HH, HH, sw, HH, HH, 64, acc, As, Bs);
    int trow = threadIdx.x >> 4, tcol = threadIdx.x & 15;
#pragma unroll
    for (int i = 0; i < 4; i++) {
        int m = m0 + trow * 4 + i;
#pragma unroll
        for (int j = 0; j < 4; j++) {
            int n = tcol * 4 + j;
            g_hid[(size_t)m * HSS + n] = fmaxf(acc[i][j] + sb[n], 0.f);
        }
    }
}

__global__ __launch_bounds__(256) void k_theme2(const float* __restrict__ rsw,
                                                const float* __restrict__ rsb)
{
    __shared__ float As[16 * 64];
    __shared__ float Bs[16 * 64];
    int n0 = blockIdx.x * 64;
    int m0 = blockIdx.y * 64;
    float acc[4][4] = {};
    gemm64(g_hid + (size_t)m0 * HSS, HSS, rsw + (size_t)n0 * HSS, HSS, HSS, 64, acc, As, Bs);
    int trow = threadIdx.x >> 4, tcol = threadIdx.x & 15;
#pragma unroll
    for (int i = 0; i < 4; i++) {
        int m = m0 + trow * 4 + i;
#pragma unroll
        for (int j = 0; j < 4; j++) {
            int n = n0 + tcol * 4 + j;
            g_theme[(size_t)m * HH + n] = sigmoidf(acc[i][j] + rsb[n]);
        }
    }
}

// ---------------- conv einsum as batched NT GEMM + fused local/rnn epilogue ----------------
__global__ __launch_bounds__(256, 2) void k_conv(const float* __restrict__ conv_b)
{
    __shared__ float As[16][128];
    __shared__ float Bs[16][128];
    int t = blockIdx.z;
    int tid = threadIdx.x;
    int lrow = tid >> 2, lcol = (tid & 3) << 2;
    int trow = tid >> 4, tcol = tid & 15;
    int b0 = blockIdx.y * 128;
    int o0 = blockIdx.x * 128;
    const float* A0 = g_A + (size_t)t * (BB * HH * CSS) + (size_t)b0 * (HH * CSS);
    const float* B0 = g_convT + (size_t)o0 * (HH * CSS);
    float acc[8][8] = {};
    for (int k0 = 0; k0 < HH * CSS; k0 += 16) {
#pragma unroll
        for (int r = 0; r < 128; r += 64) {
            float4 a4 = *reinterpret_cast<const float4*>(A0 + (size_t)(lrow + r) * (HH * CSS) + k0 + lcol);
            As[lcol + 0][lrow + r] = a4.x;
            As[lcol + 1][lrow + r] = a4.y;
            As[lcol + 2][lrow + r] = a4.z;
            As[lcol + 3][lrow + r] = a4.w;
            float4 b4 = *reinterpret_cast<const float4*>(B0 + (size_t)(lrow + r) * (HH * CSS) + k0 + lcol);
            Bs[lcol + 0][lrow + r] = b4.x;
            Bs[lcol + 1][lrow + r] = b4.y;
            Bs[lcol + 2][lrow + r] = b4.z;
            Bs[lcol + 3][lrow + r] = b4.w;
        }
        __syncthreads();
#pragma unroll
        for (int p = 0; p < 16; p++) {
            float ar[8], br[8];
#pragma unroll
            for (int i = 0; i < 8; i++) ar[i] = As[p][trow * 8 + i];
#pragma unroll
            for (int j = 0; j < 8; j++) br[j] = Bs[p][tcol * 8 + j];
#pragma unroll
            for (int i = 0; i < 8; i++)
#pragma unroll
                for (int j = 0; j < 8; j++)
                    acc[i][j] = fmaf(ar[i], br[j], acc[i][j]);
        }
        __syncthreads();
    }
#pragma unroll
    for (int i = 0; i < 8; i++) {
        int b = b0 + trow * 8 + i;
        size_t tb = (size_t)t * BB + b;
#pragma unroll
        for (int j = 0; j < 8; j++) {
            int o = o0 + tcol * 8 + j;
            g_rnn[((size_t)b * VV + t) * HH + o] =
                g_theme[tb * HH + o] * (acc[i][j] + conv_b[o]) + g_hs[tb * HH + o];
        }
    }
}

// ---------------- final out GEMM (split-K, deterministic reduce) ----------------
__global__ __launch_bounds__(256) void k_out(const float* __restrict__ ow)
{
    __shared__ float As[16 * 64];
    __shared__ float Bs[16 * 64];
    int n0 = blockIdx.x * 64;     // < 128
    int m0 = blockIdx.y * 64;     // < 256
    int z = blockIdx.z;           // 16 K-chunks of 1200
    float acc[4][4] = {};
    gemm64(g_rnn + (size_t)m0 * (VV * HH) + z * 1200, VV * HH,
           ow + (size_t)n0 * (VV * HH) + z * 1200, VV * HH, 1200, 64, acc, As, Bs);
    int trow = threadIdx.x >> 4, tcol = threadIdx.x & 15;
#pragma unroll
    for (int i = 0; i < 4; i++) {
        int m = m0 + trow * 4 + i;
#pragma unroll
        for (int j = 0; j < 4; j++) {
            int n = n0 + tcol * 4 + j;
            g_outPart[((size_t)z * BB + m) * OUTT + n] = acc[i][j];
        }
    }
}

__global__ void k_reduce(const float* __restrict__ out_b, float* __restrict__ outp, int total)
{
    int idx = blockIdx.x * 256 + threadIdx.x;
    if (idx >= total) return;
    if (idx < BB * OUTT) {
        float s = out_b[idx & (OUTT - 1)];
#pragma unroll
        for (int z = 0; z < 16; z++) s += g_outPart[(size_t)z * (BB * OUTT) + idx];
        outp[idx] = s;
    } else if (idx < BB * OUTT + VV * BB) {
        outp[idx] = g_dists[idx - BB * OUTT];
    }
}

// ---------------- launch ----------------
extern "C" void kernel_launch(void* const* d_in, const int* in_sizes, int n_in,
                              void* d_out, int out_size)
{
    const int*   node_ids  = (const int*)d_in[0];
    const float* timev     = (const float*)d_in[3];
    const float* embed     = (const float*)d_in[6];
    const float* kernel_w  = (const float*)d_in[7];
    const float* kernel_b  = (const float*)d_in[8];
    const float* rec_w     = (const float*)d_in[9];
    const float* rec_b     = (const float*)d_in[10];
    const float* scale_w   = (const float*)d_in[11];
    const float* scale_b   = (const float*)d_in[12];
    const float* rescale_w = (const float*)d_in[13];
    const float* rescale_b = (const float*)d_in[14];
    const float* conv_w    = (const float*)d_in[15];
    const float* conv_b    = (const float*)d_in[16];
    const float* out_w     = (const float*)d_in[17];
    const float* out_b     = (const float*)d_in[18];
    float* outp = (float*)d_out;

    // prep: pad/transpose weights + zero h,c  (total 8,661,528 elements)
    long prep_total = (long)GG * NDI + (long)GG * HH + GG + (long)HH * HH * CSS + 2L * BB * HH;
    int prep_blocks = (int)((prep_total + 255) / 256);
    k_prep<<<prep_blocks, 256>>>(kernel_w, rec_w, conv_w);

    // big input GEMM (gather fused), all 50 steps at once
    k_gemm_xo<<<dim3(13, 100), 256>>>(node_ids, embed, kernel_b, rec_b, timev);

    // sequential recurrence
    for (int t = 0; t < VV; ++t) {
        k_rec<<<dim3(25, 4), 256>>>(t);
        k_gates<<<BB, 128>>>(t);
    }

    // parallel post-processing over all t
    k_ld<<<50, 256>>>();
    k_abuild<<<(int)(((long)VV * BB * HH * CSS + 255) / 256), 256>>>();
    k_mh<<<(int)(((long)VV * BB * HH + 255) / 256), 256>>>();
    k_theme1<<<dim3(1, 200), 256>>>(scale_w, scale_b);
    k_theme2<<<dim3(6, 200), 256>>>(rescale_w, rescale_b);
    k_conv<<<dim3(3, 2, VV), 256>>>(conv_b);
    k_out<<<dim3(2, 4, 16), 256>>>(out_w);
    k_reduce<<<(out_size + 255) / 256, 256>>>(out_b, outp, out_size);
}

// round 2
// speedup vs baseline: 1.0017x; 1.0017x over previous
#include <cuda_runtime.h>
#include <cuda_bf16.h>
#include <cstdint>

// Problem dims
#define BB   256
#define VV   50
#define NNODE 32
#define DD   128
#define NDI  4096
#define HH   384
#define LL   12
#define CSS  10
#define GG   1560
#define HSS  64
#define OUTT 128

// ---------------- scratch (static device globals; no allocation) ----------------
__device__ float g_Wk[(size_t)GG * NDI];        // kernel_w[:, :4096] padded (stride 4096)
__device__ float g_WsumT[GG];                   // kernel_w[:,4096] + rec_w[:,384]
__device__ float g_Wr[(size_t)GG * HH];         // rec_w[:, :384]
__device__ float g_XO[(size_t)VV * BB * GG];    // [v][b][g]  precomputed input part (+biases+time)
__device__ float g_xobuf[BB * GG];              // current step xo
__device__ float g_h[BB * HH];
__device__ float g_c[BB * HH];
__device__ float g_hs[(size_t)VV * BB * HH];    // [t][b][h]
__device__ float g_dists[VV * BB];              // [t][b]
__device__ float g_ld[VV * BB * CSS];           // [t][b][k]
__device__ float g_A[(size_t)VV * BB * HH * CSS];   // [t][b][k*384+h] = hs*ld
__device__ float g_mh[(size_t)VV * BB * HH];
__device__ float g_hid[(size_t)VV * BB * HSS];
__device__ float g_theme[(size_t)VV * BB * HH];
__device__ float g_convT[(size_t)HH * HH * CSS];    // [o][k][h]
__device__ float g_rnn[(size_t)BB * VV * HH];       // [b][v][h]
__device__ float g_outPart[16 * BB * OUTT];

__device__ __forceinline__ float sigmoidf(float x) { return 1.f / (1.f + expf(-x)); }

// ---------------- prep: pad weights, transpose conv_w, zero state ----------------
__global__ void k_prep(const float* __restrict__ kw, const float* __restrict__ rw,
                       const float* __restrict__ cw)
{
    const long NWK = (long)GG * NDI;          // 6,389,760
    const long NWR = (long)GG * HH;           // 599,040
    const long NCT = (long)HH * HH * CSS;     // 1,474,560
    const long NZ  = 2L * BB * HH;            // 196,608
    long idx = (long)blockIdx.x * 256 + threadIdx.x;
    if (idx < NWK) {
        long g = idx / NDI, k = idx % NDI;
        g_Wk[idx] = kw[g * 4097 + k];
        return;
    }
    idx -= NWK;
    if (idx < NWR) {
        long g = idx / HH, j = idx % HH;
        g_Wr[idx] = rw[g * 385 + j];
        return;
    }
    idx -= NWR;
    if (idx < GG) {
        g_WsumT[idx] = kw[idx * 4097 + 4096] + rw[idx * 385 + 384];
        return;
    }
    idx -= GG;
    if (idx < NCT) {
        long o = idx / (HH * CSS);
        long c = idx % (HH * CSS);
        long k = c / HH, h = c % HH;
        g_convT[idx] = cw[(o * HH + h) * CSS + k];
        return;
    }
    idx -= NCT;
    if (idx < NZ) {
        if (idx < BB * HH) g_h[idx] = 0.f; else g_c[idx - BB * HH] = 0.f;
    }
}

// ---------------- big GEMM: XO[v][b][g] = x[bv] . Wk[g] + kb+rb + time*(WkT+WrT) ----
// fused embedding gather in A-tile load. M=12800 (bv), N=1560 (g), K=4096.
__global__ __launch_bounds__(256, 2) void k_gemm_xo(const int* __restrict__ ids,
    const float* __restrict__ embed, const float* __restrict__ kb,
    const float* __restrict__ rb, const float* __restrict__ tv)
{
    __shared__ float As[16][128];
    __shared__ float Bs[16][128];
    int tid = threadIdx.x;
    int bn = blockIdx.x, bm = blockIdx.y;
    int lrow = tid >> 2;             // 0..63
    int lcol = (tid & 3) << 2;       // 0,4,8,12
    int trow = tid >> 4, tcol = tid & 15;
    int m0 = bm * 128, g0 = bn * 128;
    float acc[8][8] = {};

    for (int k0 = 0; k0 < NDI; k0 += 16) {
#pragma unroll
        for (int r = 0; r < 128; r += 64) {
            int m = m0 + lrow + r;
            int kk = k0 + lcol;
            int id = ids[m * NNODE + (kk >> 7)];
            float4 a4 = *reinterpret_cast<const float4*>(embed + (size_t)id * DD + (kk & 127));
            As[lcol + 0][lrow + r] = a4.x;
            As[lcol + 1][lrow + r] = a4.y;
            As[lcol + 2][lrow + r] = a4.z;
            As[lcol + 3][lrow + r] = a4.w;
            int g = g0 + lrow + r;
            float4 b4 = make_float4(0.f, 0.f, 0.f, 0.f);
            if (g < GG)
                b4 = *reinterpret_cast<const float4*>(g_Wk + (size_t)g * NDI + k0 + lcol);
            Bs[lcol + 0][lrow + r] = b4.x;
            Bs[lcol + 1][lrow + r] = b4.y;
            Bs[lcol + 2][lrow + r] = b4.z;
            Bs[lcol + 3][lrow + r] = b4.w;
        }
        __syncthreads();
#pragma unroll
        for (int p = 0; p < 16; p++) {
            float ar[8], br[8];
#pragma unroll
            for (int i = 0; i < 8; i++) ar[i] = As[p][trow * 8 + i];
#pragma unroll
            for (int j = 0; j < 8; j++) br[j] = Bs[p][tcol * 8 + j];
#pragma unroll
            for (int i = 0; i < 8; i++)
#pragma unroll
                for (int j = 0; j < 8; j++)
                    acc[i][j] = fmaf(ar[i], br[j], acc[i][j]);
        }
        __syncthreads();
    }
#pragma unroll
    for (int i = 0; i < 8; i++) {
        int m = m0 + trow * 8 + i;          // m = b*50 + v
        int b = m / VV, v = m % VV;
        float tval = tv[m];                 // time[b][v]
#pragma unroll
        for (int j = 0; j < 8; j++) {
            int g = g0 + tcol * 8 + j;
            if (g < GG)
                g_XO[((size_t)v * BB + b) * GG + g] =
                    acc[i][j] + kb[g] + rb[g] + tval * g_WsumT[g];
        }
    }
}

// ---------------- generic 64x64 NT tile: C = A(64xK) * B(64xK)^T, 256 thr, TM=TN=4 ----
__device__ __forceinline__ void gemm64(const float* __restrict__ A, int lda,
                                       const float* __restrict__ Bm, int ldb,
                                       int K, int brows, float (&acc)[4][4],
                                       float* As, float* Bs)
{
    int tid = threadIdx.x;
    int lrow = tid >> 2;
    int lcol = (tid & 3) << 2;
    int trow = tid >> 4;
    int tcol = tid & 15;
    for (int k0 = 0; k0 < K; k0 += 16) {
        float4 a4 = *reinterpret_cast<const float4*>(A + (size_t)lrow * lda + k0 + lcol);
        float4 b4 = make_float4(0.f, 0.f, 0.f, 0.f);
        if (lrow < brows)
            b4 = *reinterpret_cast<const float4*>(Bm + (size_t)lrow * ldb + k0 + lcol);
        As[(lcol + 0) * 64 + lrow] = a4.x;
        As[(lcol + 1) * 64 + lrow] = a4.y;
        As[(lcol + 2) * 64 + lrow] = a4.z;
        As[(lcol + 3) * 64 + lrow] = a4.w;
        Bs[(lcol + 0) * 64 + lrow] = b4.x;
        Bs[(lcol + 1) * 64 + lrow] = b4.y;
        Bs[(lcol + 2) * 64 + lrow] = b4.z;
        Bs[(lcol + 3) * 64 + lrow] = b4.w;
        __syncthreads();
#pragma unroll
        for (int p = 0; p < 16; p++) {
            float ar[4], br[4];
#pragma unroll
            for (int i = 0; i < 4; i++) ar[i] = As[p * 64 + trow * 4 + i];
#pragma unroll
            for (int j = 0; j < 4; j++) br[j] = Bs[p * 64 + tcol * 4 + j];
#pragma unroll
            for (int i = 0; i < 4; i++)
#pragma unroll
                for (int j = 0; j < 4; j++)
                    acc[i][j] = fmaf(ar[i], br[j], acc[i][j]);
        }
        __syncthreads();
    }
}

// ---------------- per-step: xo = XO[t] + h @ Wr^T ----------------
__global__ __launch_bounds__(256) void k_rec(int t)
{
    __shared__ float As[16 * 64];
    __shared__ float Bs[16 * 64];
    int g0 = blockIdx.x * 64;
    int b0 = blockIdx.y * 64;
    float acc[4][4] = {};
    int brows = GG - g0; if (brows > 64) brows = 64;
    gemm64(g_h + (size_t)b0 * HH, HH, g_Wr + (size_t)g0 * HH, HH, HH, brows, acc, As, Bs);
    int trow = threadIdx.x >> 4, tcol = threadIdx.x & 15;
#pragma unroll
    for (int i = 0; i < 4; i++) {
        int b = b0 + trow * 4 + i;
#pragma unroll
        for (int j = 0; j < 4; j++) {
            int g = g0 + tcol * 4 + j;
            if (g < GG)
                g_xobuf[b * GG + g] = acc[i][j] + g_XO[((size_t)t * BB + b) * GG + g];
        }
    }
}

// ---------------- per-step: gates + cell update ----------------
__global__ void k_gates(int t)
{
    int b = blockIdx.x;
    int tid = threadIdx.x;   // 128
    __shared__ float sfm[LL], sim[LL];
    const float* xo = g_xobuf + b * GG;
    if (tid == 0) {
        float v[LL], mx = -1e30f;
#pragma unroll
        for (int i = 0; i < LL; i++) { v[i] = xo[i]; mx = fmaxf(mx, v[i]); }
        float s = 0.f;
#pragma unroll
        for (int i = 0; i < LL; i++) { v[i] = expf(v[i] - mx); s += v[i]; }
        float inv = 1.f / s, run = 0.f, fsum = 0.f;
#pragma unroll
        for (int i = 0; i < LL; i++) { run += v[i] * inv; sfm[i] = run; fsum += run; }
        g_dists[t * BB + b] = 1.f - fsum / (float)LL;
    } else if (tid == 32) {
        float v[LL], mx = -1e30f;
#pragma unroll
        for (int i = 0; i < LL; i++) { v[i] = xo[LL + i]; mx = fmaxf(mx, v[i]); }
        float s = 0.f;
#pragma unroll
        for (int i = 0; i < LL; i++) { v[i] = expf(v[i] - mx); s += v[i]; }
        float inv = 1.f / s, run = 0.f;
#pragma unroll
        for (int i = LL - 1; i >= 0; i--) { run += v[i] * inv; sim[i] = run; }
    }
    __syncthreads();
#pragma unroll
    for (int r = 0; r < 3; r++) {
        int hh = tid + r * 128;
        int l = hh >> 5;
        float fg = sigmoidf(xo[24 + hh]);
        float ig = sigmoidf(xo[24 + 384 + hh]);
        float og = sigmoidf(xo[24 + 768 + hh]);
        float ci = tanhf(xo[24 + 1152 + hh]);
        float fmv = sfm[l], imv = sim[l], ov = fmv * imv;
        float c = g_c[b * HH + hh];
        float cn = ov * (fg * c + ig * ci) + (fmv - ov) * c + (imv - ov) * ci;
        float hv = og * tanhf(cn);
        g_c[b * HH + hh] = cn;
        g_h[b * HH + hh] = hv;
        g_hs[((size_t)t * BB + b) * HH + hh] = hv;
    }
}

// ---------------- post: ld[t][b][k] = softmax_k(cumsum(tmp_dis)) ----------------
__global__ void k_ld()
{
    int idx = blockIdx.x * 256 + threadIdx.x;   // < 12800
    int t = idx / BB, b = idx % BB;
    float cum[CSS], run = 0.f;
#pragma unroll
    for (int k = 0; k < CSS; k++) {
        int s = t - (CSS - 1) + k;
        float d = (s >= 0) ? g_dists[s * BB + b] : 0.f;
        run += d;
        cum[k] = run;
    }
    float mx = cum[0];
#pragma unroll
    for (int k = 1; k < CSS; k++) mx = fmaxf(mx, cum[k]);
    float e[CSS], s = 0.f;
#pragma unroll
    for (int k = 0; k < CSS; k++) { e[k] = expf(cum[k] - mx); s += e[k]; }
    float inv = 1.f / s;
#pragma unroll
    for (int k = 0; k < CSS; k++) g_ld[(size_t)idx * CSS + k] = e[k] * inv;
}

// ---------------- post: A[t][b][k*384+h] = hs[t-9+k][b][h] * ld[t][b][k] ----------------
__global__ void k_abuild()
{
    long idx = (long)blockIdx.x * 256 + threadIdx.x;   // < 49,152,000
    int t = (int)(idx / (BB * HH * CSS));
    int r = (int)(idx % (BB * HH * CSS));
    int b = r / (HH * CSS);
    int c = r % (HH * CSS);
    int k = c / HH, h = c % HH;
    int s = t - (CSS - 1) + k;
    float v = 0.f;
    if (s >= 0)
        v = g_hs[((size_t)s * BB + b) * HH + h] * g_ld[((size_t)t * BB + b) * CSS + k];
    g_A[idx] = v;
}

// ---------------- post: mh = mean_k lh ----------------
__global__ void k_mh()
{
    long idx = (long)blockIdx.x * 256 + threadIdx.x;   // < 4,915,200
    int t = (int)(idx / (BB * HH));
    int r = (int)(idx % (BB * HH));
    int b = r / HH, h = r % HH;
    float s = 0.f;
    size_t base = (size_t)t * (BB * HH * CSS) + (size_t)b * (HH * CSS) + h;
#pragma unroll
    for (int k = 0; k < CSS; k++) s += g_A[base + (size_t)k * HH];
    g_mh[idx] = s * 0.1f;
}

// ---------------- theme MLP (two small GEMMs) ----------------
__global__ __launch_bounds__(256) void k_theme1(const float* __restrict__ sw,
                                                const float* __restrict__ sb)
{
    __shared__ float As[16 * 64];
    __shared__ float Bs[16 * 64];
    int m0 = blockIdx.y * 64;
    float acc[4][4] = {};
    gemm64(g_mh + (size_t)m0 * HH, HH, sw, HH, HH, 64, acc, As, Bs);
    int trow = threadIdx.x >> 4, tcol = threadIdx.x & 15;
#pragma unroll
    for (int i = 0; i < 4; i++) {
        int m = m0 + trow * 4 + i;
#pragma unroll
        for (int j = 0; j < 4; j++) {
            int n = tcol * 4 + j;
            g_hid[(size_t)m * HSS + n] = fmaxf(acc[i][j] + sb[n], 0.f);
        }
    }
}

__global__ __launch_bounds__(256) void k_theme2(const float* __restrict__ rsw,
                                                const float* __restrict__ rsb)
{
    __shared__ float As[16 * 64];
    __shared__ float Bs[16 * 64];
    int n0 = blockIdx.x * 64;
    int m0 = blockIdx.y * 64;
    float acc[4][4] = {};
    gemm64(g_hid + (size_t)m0 * HSS, HSS, rsw + (size_t)n0 * HSS, HSS, HSS, 64, acc, As, Bs);
    int trow = threadIdx.x >> 4, tcol = threadIdx.x & 15;
#pragma unroll
    for (int i = 0; i < 4; i++) {
        int m = m0 + trow * 4 + i;
#pragma unroll
        for (int j = 0; j < 4; j++) {
            int n = n0 + tcol * 4 + j;
            g_theme[(size_t)m * HH + n] = sigmoidf(acc[i][j] + rsb[n]);
        }
    }
}

// ---------------- conv einsum as batched NT GEMM + fused local/rnn epilogue ----------------
__global__ __launch_bounds__(256, 2) void k_conv(const float* __restrict__ conv_b)
{
    __shared__ float As[16][128];
    __shared__ float Bs[16][128];
    int t = blockIdx.z;
    int tid = threadIdx.x;
    int lrow = tid >> 2, lcol = (tid & 3) << 2;
    int trow = tid >> 4, tcol = tid & 15;
    int b0 = blockIdx.y * 128;
    int o0 = blockIdx.x * 128;
    const float* A0 = g_A + (size_t)t * (BB * HH * CSS) + (size_t)b0 * (HH * CSS);
    const float* B0 = g_convT + (size_t)o0 * (HH * CSS);
    float acc[8][8] = {};
    for (int k0 = 0; k0 < HH * CSS; k0 += 16) {
#pragma unroll
        for (int r = 0; r < 128; r += 64) {
            float4 a4 = *reinterpret_cast<const float4*>(A0 + (size_t)(lrow + r) * (HH * CSS) + k0 + lcol);
            As[lcol + 0][lrow + r] = a4.x;
            As[lcol + 1][lrow + r] = a4.y;
            As[lcol + 2][lrow + r] = a4.z;
            As[lcol + 3][lrow + r] = a4.w;
            float4 b4 = *reinterpret_cast<const float4*>(B0 + (size_t)(lrow + r) * (HH * CSS) + k0 + lcol);
            Bs[lcol + 0][lrow + r] = b4.x;
            Bs[lcol + 1][lrow + r] = b4.y;
            Bs[lcol + 2][lrow + r] = b4.z;
            Bs[lcol + 3][lrow + r] = b4.w;
        }
        __syncthreads();
#pragma unroll
        for (int p = 0; p < 16; p++) {
            float ar[8], br[8];
#pragma unroll
            for (int i = 0; i < 8; i++) ar[i] = As[p][trow * 8 + i];
#pragma unroll
            for (int j = 0; j < 8; j++) br[j] = Bs[p][tcol * 8 + j];
#pragma unroll
            for (int i = 0; i < 8; i++)
#pragma unroll
                for (int j = 0; j < 8; j++)
                    acc[i][j] = fmaf(ar[i], br[j], acc[i][j]);
        }
        __syncthreads();
    }
#pragma unroll
    for (int i = 0; i < 8; i++) {
        int b = b0 + trow * 8 + i;
        size_t tb = (size_t)t * BB + b;
#pragma unroll
        for (int j = 0; j < 8; j++) {
            int o = o0 + tcol * 8 + j;
            g_rnn[((size_t)b * VV + t) * HH + o] =
                g_theme[tb * HH + o] * (acc[i][j] + conv_b[o]) + g_hs[tb * HH + o];
        }
    }
}

// ---------------- final out GEMM (split-K, deterministic reduce) ----------------
__global__ __launch_bounds__(256) void k_out(const float* __restrict__ ow)
{
    __shared__ float As[16 * 64];
    __shared__ float Bs[16 * 64];
    int n0 = blockIdx.x * 64;     // < 128
    int m0 = blockIdx.y * 64;     // < 256
    int z = blockIdx.z;           // 16 K-chunks of 1200
    float acc[4][4] = {};
    gemm64(g_rnn + (size_t)m0 * (VV * HH) + z * 1200, VV * HH,
           ow + (size_t)n0 * (VV * HH) + z * 1200, VV * HH, 1200, 64, acc, As, Bs);
    int trow = threadIdx.x >> 4, tcol = threadIdx.x & 15;
#pragma unroll
    for (int i = 0; i < 4; i++) {
        int m = m0 + trow * 4 + i;
#pragma unroll
        for (int j = 0; j < 4; j++) {
            int n = n0 + tcol * 4 + j;
            g_outPart[((size_t)z * BB + m) * OUTT + n] = acc[i][j];
        }
    }
}

__global__ void k_reduce(const float* __restrict__ out_b, float* __restrict__ outp, int total)
{
    int idx = blockIdx.x * 256 + threadIdx.x;
    if (idx >= total) return;
    if (idx < BB * OUTT) {
        float s = out_b[idx & (OUTT - 1)];
#pragma unroll
        for (int z = 0; z < 16; z++) s += g_outPart[(size_t)z * (BB * OUTT) + idx];
        outp[idx] = s;
    } else if (idx < BB * OUTT + VV * BB) {
        outp[idx] = g_dists[idx - BB * OUTT];
    }
}

// ---------------- launch ----------------
extern "C" void kernel_launch(void* const* d_in, const int* in_sizes, int n_in,
                              void* d_out, int out_size)
{
    const int*   node_ids  = (const int*)d_in[0];
    const float* timev     = (const float*)d_in[3];
    const float* embed     = (const float*)d_in[6];
    const float* kernel_w  = (const float*)d_in[7];
    const float* kernel_b  = (const float*)d_in[8];
    const float* rec_w     = (const float*)d_in[9];
    const float* rec_b     = (const float*)d_in[10];
    const float* scale_w   = (const float*)d_in[11];
    const float* scale_b   = (const float*)d_in[12];
    const float* rescale_w = (const float*)d_in[13];
    const float* rescale_b = (const float*)d_in[14];
    const float* conv_w    = (const float*)d_in[15];
    const float* conv_b    = (const float*)d_in[16];
    const float* out_w     = (const float*)d_in[17];
    const float* out_b     = (const float*)d_in[18];
    float* outp = (float*)d_out;

    // prep: pad/transpose weights + zero h,c  (total 8,661,528 elements)
    long prep_total = (long)GG * NDI + (long)GG * HH + GG + (long)HH * HH * CSS + 2L * BB * HH;
    int prep_blocks = (int)((prep_total + 255) / 256);
    k_prep<<<prep_blocks, 256>>>(kernel_w, rec_w, conv_w);

    // big input GEMM (gather fused), all 50 steps at once
    k_gemm_xo<<<dim3(13, 100), 256>>>(node_ids, embed, kernel_b, rec_b, timev);

    // sequential recurrence
    for (int t = 0; t < VV; ++t) {
        k_rec<<<dim3(25, 4), 256>>>(t);
        k_gates<<<BB, 128>>>(t);
    }

    // parallel post-processing over all t
    k_ld<<<50, 256>>>();
    k_abuild<<<(int)(((long)VV * BB * HH * CSS + 255) / 256), 256>>>();
    k_mh<<<(int)(((long)VV * BB * HH + 255) / 256), 256>>>();
    k_theme1<<<dim3(1, 200), 256>>>(scale_w, scale_b);
    k_theme2<<<dim3(6, 200), 256>>>(rescale_w, rescale_b);
    k_conv<<<dim3(3, 2, VV), 256>>>(conv_b);
    k_out<<<dim3(2, 4, 16), 256>>>(out_w);
    k_reduce<<<(out_size + 255) / 256, 256>>>(out_b, outp, out_size);
}

// round 3
// speedup vs baseline: 1.4645x; 1.4620x over previous
#include <cuda_runtime.h>
#include <cuda_bf16.h>
#include <cstdint>

#define BB 256
#define VV 50
#define NNODE 32
#define DD 128
#define NDI 4096
#define HH 384
#define LL 12
#define CSS 10
#define GG 1560
#define GPAD 1792
#define HSS 64
#define OUTT 128
#define NQ 3840
#define LDT 40
#define NBLK 100

typedef __nv_bfloat16 bf;

__device__ bf g_WkH[(size_t)GPAD*NDI], g_WkL[(size_t)GPAD*NDI];
__device__ bf g_embH[10001*DD], g_embL[10001*DD];
__device__ bf g_WcH[(size_t)NQ*HH], g_WcL[(size_t)NQ*HH];
__device__ bf g_hsH[(size_t)VV*BB*HH], g_hsL[(size_t)VV*BB*HH];
__device__ float g_bias[GG], g_WsumT[GG];
__device__ float g_Wr[(size_t)GG*HH];
__device__ float g_XO[(size_t)VV*BB*GG];
__device__ float g_xobuf[BB*GG];
__device__ float g_h[BB*HH], g_c[BB*HH];
__device__ float g_hs[(size_t)VV*BB*HH];
__device__ float g_dists[VV*BB];
__device__ float g_ld[VV*BB*CSS];
__device__ float g_Q[(size_t)VV*BB*NQ];
__device__ float g_mh[(size_t)VV*BB*HH];
__device__ float g_hid[(size_t)VV*BB*HSS];
__device__ float g_theme[(size_t)VV*BB*HH];
__device__ float g_rnn[(size_t)BB*VV*HH];
__device__ float g_outPart[16*BB*OUTT];
__device__ unsigned g_barCount, g_barGen;

__device__ __forceinline__ float sigmoidf(float x){ return 1.f/(1.f+expf(-x)); }
__device__ __forceinline__ void bsplit(float v, bf& hi, bf& lo){
    bf h = __float2bfloat16(v); hi = h; lo = __float2bfloat16(v - __bfloat162float(h));
}
__device__ __forceinline__ void cpasync16(void* dst, const void* src){
    unsigned d = (unsigned)__cvta_generic_to_shared(dst);
    asm volatile("cp.async.cg.shared.global [%0], [%1], 16;" :: "r"(d), "l"(src));
}
__device__ __forceinline__ void ldsm4(unsigned* r, const void* p){
    unsigned a = (unsigned)__cvta_generic_to_shared(p);
    asm volatile("ldmatrix.sync.aligned.m8n8.x4.shared.b16 {%0,%1,%2,%3}, [%4];"
        : "=r"(r[0]),"=r"(r[1]),"=r"(r[2]),"=r"(r[3]) : "r"(a));
}
__device__ __forceinline__ void mma16816(float* c, const unsigned* a, unsigned b0, unsigned b1){
    asm volatile("mma.sync.aligned.m16n8k16.row.col.f32.bf16.bf16.f32 "
        "{%0,%1,%2,%3}, {%4,%5,%6,%7}, {%8,%9}, {%0,%1,%2,%3};"
        : "+f"(c[0]),"+f"(c[1]),"+f"(c[2]),"+f"(c[3])
        : "r"(a[0]),"r"(a[1]),"r"(a[2]),"r"(a[3]), "r"(b0),"r"(b1));
}

// ---------------- prep ----------------
__global__ void k_prep(const float* __restrict__ kw, const float* __restrict__ rw,
                       const float* __restrict__ cw, const float* __restrict__ kb,
                       const float* __restrict__ rb, const float* __restrict__ em)
{
    const long R1=(long)GPAD*NDI, R2=10001L*DD, R3=(long)NQ*HH, R4=GG, R5=(long)GG*HH, R6=2L*BB*HH;
    long i = (long)blockIdx.x*256 + threadIdx.x;
    if (i < R1){ long g=i/NDI,k=i%NDI; float v=(g<GG)?kw[g*4097+k]:0.f; bsplit(v,g_WkH[i],g_WkL[i]); return; }
    i-=R1;
    if (i < R2){ bsplit(em[i],g_embH[i],g_embL[i]); return; }
    i-=R2;
    if (i < R3){ long n=i/HH,h=i%HH; long k=n/HH,o=n%HH;
        bsplit(cw[o*HH*CSS + h*CSS + k], g_WcH[i], g_WcL[i]); return; }
    i-=R3;
    if (i < R4){ g_bias[i]=kb[i]+rb[i]; g_WsumT[i]=kw[i*4097+4096]+rw[i*385+384]; return; }
    i-=R4;
    if (i < R5){ long g=i/HH,j=i%HH; g_Wr[i]=rw[g*385+j]; return; }
    i-=R5;
    if (i < R6){ if(i<BB*HH) g_h[i]=0.f; else g_c[i-BB*HH]=0.f; return; }
    i-=R6;
    if (i==0){ g_barCount=0u; g_barGen=0u; }
}

// -------- shared bf16 split-3 MMA kernel: C(128x256) += A(128xK) * B(256xK)^T --------
// MODE 0: big input GEMM (A = gathered embeddings, B = Wk, K=4096, epilogue XO)
// MODE 1: conv Q GEMM   (A = hs bf16,            B = Wc, K=384,  epilogue Q)
template<int MODE>
__global__ void __launch_bounds__(256) k_mma(const int* __restrict__ ids, const float* __restrict__ tv)
{
    extern __shared__ bf smem[];
    bf* AsH = smem;
    bf* AsL = AsH + 2*128*LDT;
    bf* BsH = AsL + 2*128*LDT;
    bf* BsL = BsH + 2*256*LDT;
    const int tid=threadIdx.x, lane=tid&31, w=tid>>5, wm=w>>2, wn=w&3;
    const int m0=blockIdx.y*128, n0=blockIdx.x*256;
    const int KTOT = (MODE==0)?NDI:HH;
    const int KCH = KTOT/32;
    float c[4][8][4];
#pragma unroll
    for(int a=0;a<4;a++)
#pragma unroll
        for(int b=0;b<8;b++)
#pragma unroll
            for(int q=0;q<4;q++) c[a][b][q]=0.f;

    auto load = [&](int ci, int buf){
        int k0 = ci*32;
        for (int s=tid; s<3072; s+=256){
            if (s<1024){
                int row=s>>3, p=s&7, part=p&3;
                const bf *sH, *sL;
                if (MODE==0){
                    int id = ids[(m0+row)*NNODE + (k0>>7)];
                    size_t so = (size_t)id*DD + (k0&127) + part*8;
                    sH = g_embH+so; sL = g_embL+so;
                } else {
                    size_t so = (size_t)(m0+row)*HH + k0 + part*8;
                    sH = g_hsH+so; sL = g_hsL+so;
                }
                if (p<4) cpasync16(AsH+(buf*128+row)*LDT+part*8, sH);
                else     cpasync16(AsL+(buf*128+row)*LDT+part*8, sL);
            } else {
                int s2=s-1024, row=s2>>3, p=s2&7, part=p&3;
                size_t so = (MODE==0) ? (size_t)(n0+row)*NDI + k0 + part*8
                                      : (size_t)(n0+row)*HH  + k0 + part*8;
                const bf* sH = ((MODE==0)?g_WkH:g_WcH)+so;
                const bf* sL = ((MODE==0)?g_WkL:g_WcL)+so;
                if (p<4) cpasync16(BsH+(buf*256+row)*LDT+part*8, sH);
                else     cpasync16(BsL+(buf*256+row)*LDT+part*8, sL);
            }
        }
    };

    load(0,0);
    asm volatile("cp.async.commit_group;");
    for (int ci=0; ci<KCH; ci++){
        if (ci+1<KCH){
            load(ci+1,(ci+1)&1);
            asm volatile("cp.async.commit_group;");
            asm volatile("cp.async.wait_group 1;");
        } else {
            asm volatile("cp.async.wait_group 0;");
        }
        __syncthreads();
        const bf* aH = AsH + (ci&1)*128*LDT;
        const bf* aL = AsL + (ci&1)*128*LDT;
        const bf* bH = BsH + (ci&1)*256*LDT;
        const bf* bL = BsL + (ci&1)*256*LDT;
#pragma unroll
        for (int ks=0; ks<32; ks+=16){
            unsigned ah[4][4], al[4][4], bb[4][4];
            int arow = wm*64 + (lane&15);
            int acol = ks + ((lane>>4)<<3);
            int brow = wn*64 + ((lane>>4)<<3) + (lane&7);
            int bcol = ks + (((lane>>3)&1)<<3);
#pragma unroll
            for(int mi=0;mi<4;mi++) ldsm4(ah[mi], aH + (arow+mi*16)*LDT + acol);
#pragma unroll
            for(int gi=0;gi<4;gi++) ldsm4(bb[gi], bH + (brow+gi*16)*LDT + bcol);
#pragma unroll
            for(int mi=0;mi<4;mi++)
#pragma unroll
                for(int ni=0;ni<8;ni++)
                    mma16816(c[mi][ni], ah[mi], bb[ni>>1][(ni&1)*2], bb[ni>>1][(ni&1)*2+1]);
#pragma unroll
            for(int mi=0;mi<4;mi++) ldsm4(al[mi], aL + (arow+mi*16)*LDT + acol);
#pragma unroll
            for(int mi=0;mi<4;mi++)
#pragma unroll
                for(int ni=0;ni<8;ni++)
                    mma16816(c[mi][ni], al[mi], bb[ni>>1][(ni&1)*2], bb[ni>>1][(ni&1)*2+1]);
#pragma unroll
            for(int gi=0;gi<4;gi++) ldsm4(bb[gi], bL + (brow+gi*16)*LDT + bcol);
#pragma unroll
            for(int mi=0;mi<4;mi++)
#pragma unroll
                for(int ni=0;ni<8;ni++)
                    mma16816(c[mi][ni], ah[mi], bb[ni>>1][(ni&1)*2], bb[ni>>1][(ni&1)*2+1]);
        }
        __syncthreads();
    }

#pragma unroll
    for(int mi=0;mi<4;mi++){
        int r = m0 + wm*64 + mi*16 + (lane>>2);
#pragma unroll
        for(int ni=0;ni<8;ni++){
            int n = n0 + wn*64 + ni*8 + ((lane&3)<<1);
#pragma unroll
            for(int hf=0; hf<2; hf++){
                int rr = r + hf*8;
                if (MODE==0){
                    int b = rr/VV, v = rr%VV;
                    float tval = tv[rr];
                    size_t base = ((size_t)v*BB+b)*GG;
                    if (n < GG)   g_XO[base+n]   = c[mi][ni][hf*2+0] + g_bias[n]   + tval*g_WsumT[n];
                    if (n+1 < GG) g_XO[base+n+1] = c[mi][ni][hf*2+1] + g_bias[n+1] + tval*g_WsumT[n+1];
                } else {
                    g_Q[(size_t)rr*NQ+n]   = c[mi][ni][hf*2+0];
                    g_Q[(size_t)rr*NQ+n+1] = c[mi][ni][hf*2+1];
                }
            }
        }
    }
}

// ---------------- fp32 64x64 NT tile helper ----------------
__device__ __forceinline__ void gemm64(const float* __restrict__ A, int lda,
                                       const float* __restrict__ Bm, int ldb,
                                       int K, int brows, float (&acc)[4][4],
                                       float* As, float* Bs)
{
    int tid=threadIdx.x, lrow=tid>>2, lcol=(tid&3)<<2, trow=tid>>4, tcol=tid&15;
    for (int k0=0;k0<K;k0+=16){
        float4 a4 = *reinterpret_cast<const float4*>(A + (size_t)lrow*lda + k0 + lcol);
        float4 b4 = make_float4(0.f,0.f,0.f,0.f);
        if (lrow < brows) b4 = *reinterpret_cast<const float4*>(Bm + (size_t)lrow*ldb + k0 + lcol);
        As[(lcol+0)*64+lrow]=a4.x; As[(lcol+1)*64+lrow]=a4.y;
        As[(lcol+2)*64+lrow]=a4.z; As[(lcol+3)*64+lrow]=a4.w;
        Bs[(lcol+0)*64+lrow]=b4.x; Bs[(lcol+1)*64+lrow]=b4.y;
        Bs[(lcol+2)*64+lrow]=b4.z; Bs[(lcol+3)*64+lrow]=b4.w;
        __syncthreads();
#pragma unroll
        for (int p=0;p<16;p++){
            float ar[4], br[4];
#pragma unroll
            for(int i=0;i<4;i++) ar[i]=As[p*64+trow*4+i];
#pragma unroll
            for(int j=0;j<4;j++) br[j]=Bs[p*64+tcol*4+j];
#pragma unroll
            for(int i=0;i<4;i++)
#pragma unroll
                for(int j=0;j<4;j++) acc[i][j]=fmaf(ar[i],br[j],acc[i][j]);
        }
        __syncthreads();
    }
}

// ---------------- persistent recurrence ----------------
__device__ __forceinline__ void gridBarrier()
{
    __syncthreads();
    if (threadIdx.x==0){
        __threadfence();
        volatile unsigned* genp = &g_barGen;
        unsigned gen = *genp;
        if (atomicAdd(&g_barCount,1u) == NBLK-1){
            atomicExch(&g_barCount,0u);
            __threadfence();
            *genp = gen+1;
        } else {
            while (*genp == gen) __nanosleep(32);
        }
        __threadfence();
    }
    __syncthreads();
}

__global__ void __launch_bounds__(256) k_recur()
{
    __shared__ float As[16*64], Bs[16*64];
    __shared__ float sfm[LL], sim[LL];
    const int bid=blockIdx.x, tid=threadIdx.x;
    const int g0=(bid%25)*64, b0=(bid/25)*64;
    int brows = GG-g0; if (brows>64) brows=64;

    for (int t=0;t<VV;t++){
        {   // phase A: xo = h @ Wr^T + XO[t]
            float acc[4][4] = {};
            gemm64(g_h + (size_t)b0*HH, HH, g_Wr + (size_t)g0*HH, HH, HH, brows, acc, As, Bs);
            int trow=tid>>4, tcol=tid&15;
#pragma unroll
            for(int i=0;i<4;i++){
                int b=b0+trow*4+i;
#pragma unroll
                for(int j=0;j<4;j++){
                    int g=g0+tcol*4+j;
                    if (g<GG) g_xobuf[b*GG+g] = acc[i][j] + g_XO[((size_t)t*BB+b)*GG+g];
                }
            }
        }
        gridBarrier();
        // phase B: gates + cell update (blocks split the batch)
        for (int b=bid; b<BB; b+=NBLK){
            const float* xo = g_xobuf + b*GG;
            if (tid==0){
                float v[LL], mx=-1e30f;
#pragma unroll
                for(int i=0;i<LL;i++){ v[i]=xo[i]; mx=fmaxf(mx,v[i]); }
                float s=0.f;
#pragma unroll
                for(int i=0;i<LL;i++){ v[i]=expf(v[i]-mx); s+=v[i]; }
                float inv=1.f/s, run=0.f, fsum=0.f;
#pragma unroll
                for(int i=0;i<LL;i++){ run+=v[i]*inv; sfm[i]=run; fsum+=run; }
                g_dists[t*BB+b] = 1.f - fsum/(float)LL;
            } else if (tid==32){
                float v[LL], mx=-1e30f;
#pragma unroll
                for(int i=0;i<LL;i++){ v[i]=xo[LL+i]; mx=fmaxf(mx,v[i]); }
                float s=0.f;
#pragma unroll
                for(int i=0;i<LL;i++){ v[i]=expf(v[i]-mx); s+=v[i]; }
                float inv=1.f/s, run=0.f;
#pragma unroll
                for(int i=LL-1;i>=0;i--){ run+=v[i]*inv; sim[i]=run; }
            }
            __syncthreads();
#pragma unroll
            for(int r=0;r<2;r++){
                int hh = tid + r*256;
                if (hh < HH){
                    int l = hh>>5;
                    float fg = sigmoidf(xo[24+hh]);
                    float ig = sigmoidf(xo[24+384+hh]);
                    float og = sigmoidf(xo[24+768+hh]);
                    float ci = tanhf(xo[24+1152+hh]);
                    float fmv=sfm[l], imv=sim[l], ov=fmv*imv;
                    float cold = g_c[b*HH+hh];
                    float cn = ov*(fg*cold+ig*ci) + (fmv-ov)*cold + (imv-ov)*ci;
                    float hv = og*tanhf(cn);
                    g_c[b*HH+hh]=cn; g_h[b*HH+hh]=hv;
                    size_t o = ((size_t)t*BB+b)*HH+hh;
                    g_hs[o]=hv;
                    bsplit(hv, g_hsH[o], g_hsL[o]);
                }
            }
            __syncthreads();
        }
        gridBarrier();
    }
}

// ---------------- ld weights ----------------
__global__ void k_ld()
{
    int idx = blockIdx.x*256 + threadIdx.x;   // < 12800
    int t = idx/BB, b = idx%BB;
    float cum[CSS], run=0.f;
#pragma unroll
    for(int k=0;k<CSS;k++){
        int s = t-(CSS-1)+k;
        run += (s>=0)? g_dists[s*BB+b] : 0.f;
        cum[k]=run;
    }
    float mx=cum[0];
#pragma unroll
    for(int k=1;k<CSS;k++) mx=fmaxf(mx,cum[k]);
    float e[CSS], s=0.f;
#pragma unroll
    for(int k=0;k<CSS;k++){ e[k]=expf(cum[k]-mx); s+=e[k]; }
    float inv=1.f/s;
#pragma unroll
    for(int k=0;k<CSS;k++) g_ld[(size_t)idx*CSS+k]=e[k]*inv;
}

// ---------------- mh = mean_k ld*hs ----------------
__global__ void k_mh()
{
    long idx = (long)blockIdx.x*256 + threadIdx.x;    // < 4,915,200
    int t = (int)(idx/(BB*HH));
    int r = (int)(idx%(BB*HH));
    int b = r/HH, h = r%HH;
    const float* ld = g_ld + ((size_t)t*BB+b)*CSS;
    float s=0.f;
#pragma unroll
    for(int k=0;k<CSS;k++){
        int sv = t-(CSS-1)+k;
        if (sv>=0) s += ld[k]*g_hs[((size_t)sv*BB+b)*HH+h];
    }
    g_mh[idx] = s*0.1f;
}

// ---------------- theme MLP ----------------
__global__ void __launch_bounds__(256) k_theme1(const float* __restrict__ sw, const float* __restrict__ sb)
{
    __shared__ float As[16*64], Bs[16*64];
    int m0 = blockIdx.y*64;
    float acc[4][4] = {};
    gemm64(g_mh + (size_t)m0*HH, HH, sw, HH, HH, 64, acc, As, Bs);
    int trow=threadIdx.x>>4, tcol=threadIdx.x&15;
#pragma unroll
    for(int i=0;i<4;i++){
        int m=m0+trow*4+i;
#pragma unroll
        for(int j=0;j<4;j++){
            int n=tcol*4+j;
            g_hid[(size_t)m*HSS+n] = fmaxf(acc[i][j]+sb[n], 0.f);
        }
    }
}
__global__ void __launch_bounds__(256) k_theme2(const float* __restrict__ rsw, const float* __restrict__ rsb)
{
    __shared__ float As[16*64], Bs[16*64];
    int n0 = blockIdx.x*64, m0 = blockIdx.y*64;
    float acc[4][4] = {};
    gemm64(g_hid + (size_t)m0*HSS, HSS, rsw + (size_t)n0*HSS, HSS, HSS, 64, acc, As, Bs);
    int trow=threadIdx.x>>4, tcol=threadIdx.x&15;
#pragma unroll
    for(int i=0;i<4;i++){
        int m=m0+trow*4+i;
#pragma unroll
        for(int j=0;j<4;j++){
            int n=n0+tcol*4+j;
            g_theme[(size_t)m*HH+n] = sigmoidf(acc[i][j]+rsb[n]);
        }
    }
}

// ---------------- final: rnn = theme*(conv+b) + hs ----------------
__global__ void k_final(const float* __restrict__ conv_b)
{
    long idx = (long)blockIdx.x*256 + threadIdx.x;    // < 4,915,200
    int t = (int)(idx/(BB*HH));
    int r = (int)(idx%(BB*HH));
    int b = r/HH, o = r%HH;
    const float* ld = g_ld + ((size_t)t*BB+b)*CSS;
    float conv=0.f;
#pragma unroll
    for(int k=0;k<CSS;k++){
        int sv = t-(CSS-1)+k;
        if (sv>=0) conv += ld[k]*g_Q[((size_t)sv*BB+b)*NQ + k*HH + o];
    }
    size_t tb = (size_t)t*BB+b;
    g_rnn[((size_t)b*VV+t)*HH+o] = g_theme[tb*HH+o]*(conv+conv_b[o]) + g_hs[tb*HH+o];
}

// ---------------- out GEMM (split-K) + reduce ----------------
__global__ void __launch_bounds__(256) k_out(const float* __restrict__ ow)
{
    __shared__ float As[16*64], Bs[16*64];
    int n0=blockIdx.x*64, m0=blockIdx.y*64, z=blockIdx.z;
    float acc[4][4] = {};
    gemm64(g_rnn + (size_t)m0*(VV*HH) + z*1200, VV*HH,
           ow + (size_t)n0*(VV*HH) + z*1200, VV*HH, 1200, 64, acc, As, Bs);
    int trow=threadIdx.x>>4, tcol=threadIdx.x&15;
#pragma unroll
    for(int i=0;i<4;i++){
        int m=m0+trow*4+i;
#pragma unroll
        for(int j=0;j<4;j++){
            int n=n0+tcol*4+j;
            g_outPart[((size_t)z*BB+m)*OUTT+n]=acc[i][j];
        }
    }
}
__global__ void k_reduce(const float* __restrict__ out_b, float* __restrict__ outp, int total)
{
    int idx = blockIdx.x*256 + threadIdx.x;
    if (idx >= total) return;
    if (idx < BB*OUTT){
        float s = out_b[idx & (OUTT-1)];
#pragma unroll
        for(int z=0;z<16;z++) s += g_outPart[(size_t)z*(BB*OUTT)+idx];
        outp[idx]=s;
    } else if (idx < BB*OUTT + VV*BB){
        outp[idx] = g_dists[idx - BB*OUTT];
    }
}

// ---------------- launch ----------------
extern "C" void kernel_launch(void* const* d_in, const int* in_sizes, int n_in,
                              void* d_out, int out_size)
{
    const int*   node_ids  = (const int*)d_in[0];
    const float* timev     = (const float*)d_in[3];
    const float* embed     = (const float*)d_in[6];
    const float* kernel_w  = (const float*)d_in[7];
    const float* kernel_b  = (const float*)d_in[8];
    const float* rec_w     = (const float*)d_in[9];
    const float* rec_b     = (const float*)d_in[10];
    const float* scale_w   = (const float*)d_in[11];
    const float* scale_b   = (const float*)d_in[12];
    const float* rescale_w = (const float*)d_in[13];
    const float* rescale_b = (const float*)d_in[14];
    const float* conv_b    = (const float*)d_in[16];
    const float* conv_w    = (const float*)d_in[15];
    const float* out_w     = (const float*)d_in[17];
    const float* out_b     = (const float*)d_in[18];
    float* outp = (float*)d_out;

    const int SMEM = 2*LDT*(128+128+256+256)*2;   // 122880 bytes
    static bool cfg = false;
    if (!cfg){
        cudaFuncSetAttribute(k_mma<0>, cudaFuncAttributeMaxDynamicSharedMemorySize, SMEM);
        cudaFuncSetAttribute(k_mma<1>, cudaFuncAttributeMaxDynamicSharedMemorySize, SMEM);
        cfg = true;
    }

    long prep_total = (long)GPAD*NDI + 10001L*DD + (long)NQ*HH + GG + (long)GG*HH + 2L*BB*HH + 1;
    k_prep<<<(int)((prep_total+255)/256), 256>>>(kernel_w, rec_w, conv_w, kernel_b, rec_b, embed);

    k_mma<0><<<dim3(7,100), 256, SMEM>>>(node_ids, timev);
    k_recur<<<NBLK, 256>>>();
    k_ld<<<50, 256>>>();
    k_mma<1><<<dim3(15,100), 256, SMEM>>>(node_ids, timev);
    k_mh<<<19200, 256>>>();
    k_theme1<<<dim3(1,200), 256>>>(scale_w, scale_b);
    k_theme2<<<dim3(6,200), 256>>>(rescale_w, rescale_b);
    k_final<<<19200, 256>>>(conv_b);
    k_out<<<dim3(2,4,16), 256>>>(out_w);
    k_reduce<<<(out_size+255)/256, 256>>>(out_b, outp, out_size);
}

// round 5
// speedup vs baseline: 1.7325x; 1.1830x over previous
#include <cuda_runtime.h>
#include <cuda_bf16.h>
#include <cstdint>

#define BB 256
#define VV 50
#define NNODE 32
#define DD 128
#define NDI 4096
#define HH 384
#define LL 12
#define CSS 10
#define GG 1560
#define GPAD 1792
#define HSS 64
#define OUTT 128
#define KC2 3840
#define NBLK 100
#define LDT 40

typedef __nv_bfloat16 bf;

__device__ bf g_WkH[(size_t)GPAD*NDI], g_WkL[(size_t)GPAD*NDI];
__device__ bf g_embH[10001*DD], g_embL[10001*DD];
__device__ bf g_WcH[(size_t)HH*KC2], g_WcL[(size_t)HH*KC2];
__device__ float g_bias[GG], g_WsumT[GG];
__device__ float g_Wr[(size_t)GG*HH];
__device__ float g_XO[(size_t)VV*BB*GG];
__device__ float g_xobuf[BB*GG];
__device__ float g_h[BB*HH], g_c[BB*HH];
__device__ float g_hs[(size_t)VV*BB*HH];
__device__ float g_dists[VV*BB];
__device__ float g_ld[VV*BB*CSS];
__device__ float g_mh[(size_t)VV*BB*HH];
__device__ float g_hid[(size_t)VV*BB*HSS];
__device__ float g_theme[(size_t)VV*BB*HH];
__device__ float g_rnn[(size_t)BB*VV*HH];
__device__ float g_outPart[16*BB*OUTT];
__device__ unsigned g_barCount, g_barGen;

__device__ __forceinline__ float sigmoidf(float x){ return 1.f/(1.f+expf(-x)); }
__device__ __forceinline__ void bsplit(float v, bf& hi, bf& lo){
    bf h = __float2bfloat16(v); hi = h; lo = __float2bfloat16(v - __bfloat162float(h));
}
__device__ __forceinline__ void cpa16(uint32_t dst, const void* src){
    asm volatile("cp.async.cg.shared.global [%0], [%1], 16;" :: "r"(dst), "l"(src));
}
__device__ __forceinline__ void ldsm4(unsigned* r, const bf* p){
    unsigned a = (unsigned)__cvta_generic_to_shared(p);
    asm volatile("ldmatrix.sync.aligned.m8n8.x4.shared.b16 {%0,%1,%2,%3}, [%4];"
        : "=r"(r[0]),"=r"(r[1]),"=r"(r[2]),"=r"(r[3]) : "r"(a));
}
__device__ __forceinline__ void mma16816(float* c, const unsigned* a, unsigned b0, unsigned b1){
    asm volatile("mma.sync.aligned.m16n8k16.row.col.f32.bf16.bf16.f32 "
        "{%0,%1,%2,%3}, {%4,%5,%6,%7}, {%8,%9}, {%0,%1,%2,%3};"
        : "+f"(c[0]),"+f"(c[1]),"+f"(c[2]),"+f"(c[3])
        : "r"(a[0]),"r"(a[1]),"r"(a[2]),"r"(a[3]), "r"(b0),"r"(b1));
}

// ---------------- prep ----------------
__global__ void k_prep(const float* __restrict__ kw, const float* __restrict__ rw,
                       const float* __restrict__ cw, const float* __restrict__ kb,
                       const float* __restrict__ rb, const float* __restrict__ em)
{
    const long R1=(long)GPAD*NDI, R2=10001L*DD, R3=(long)HH*KC2, R4=GG, R5=(long)GG*HH, R6=2L*BB*HH;
    long i = (long)blockIdx.x*256 + threadIdx.x;
    if (i < R1){ long g=i/NDI,k=i%NDI; float v=(g<GG)?kw[g*4097+k]:0.f; bsplit(v,g_WkH[i],g_WkL[i]); return; }
    i-=R1;
    if (i < R2){ bsplit(em[i],g_embH[i],g_embL[i]); return; }
    i-=R2;
    if (i < R3){ long o=i/KC2, c=i%KC2; long k=c/HH, h=c%HH;
        bsplit(cw[(o*HH+h)*CSS+k], g_WcH[i], g_WcL[i]); return; }
    i-=R3;
    if (i < R4){ g_bias[i]=kb[i]+rb[i]; g_WsumT[i]=kw[i*4097+4096]+rw[i*385+384]; return; }
    i-=R4;
    if (i < R5){ long g=i/HH,j=i%HH; g_Wr[i]=rw[g*385+j]; return; }
    i-=R5;
    if (i < R6){ if(i<BB*HH) g_h[i]=0.f; else g_c[i-BB*HH]=0.f; return; }
    i-=R6;
    if (i==0){ g_barCount=0u; g_barGen=0u; }
}

// -------- mma.sync split-3 bf16 GEMM: C(128x128) = A(128xK) * B(128xK)^T --------
// MODE 0: A = gathered embeddings (m=b*50+v), B = Wk,  K=4096, epi -> g_XO
// MODE 1: A = ld*hs built on the fly (m=t*256+b), B = Wc, K=3840, epi -> g_rnn
// smem: AsH[2][128][LDT], AsL, BsH, BsL  (80 KB), 2 CTAs/SM
template<int MODE>
__global__ void __launch_bounds__(256,2) k_gma(const int* __restrict__ ids,
    const float* __restrict__ tv, const float* __restrict__ cb)
{
    extern __shared__ __align__(16) bf smem[];
    bf* AsH = smem;                 // 2*128*LDT
    bf* AsL = AsH + 2*128*LDT;
    bf* BsH = AsL + 2*128*LDT;
    bf* BsL = BsH + 2*128*LDT;
    uint32_t sAH = (uint32_t)__cvta_generic_to_shared(AsH);
    uint32_t sAL = (uint32_t)__cvta_generic_to_shared(AsL);
    uint32_t sBH = (uint32_t)__cvta_generic_to_shared(BsH);
    uint32_t sBL = (uint32_t)__cvta_generic_to_shared(BsL);
    const int tid = threadIdx.x, lane = tid&31, w = tid>>5;
    const int wm = w>>2, wn = w&3;                 // warp tile 64x32
    const int m0 = blockIdx.y*128, n0 = blockIdx.x*128;
    const int KCH = (MODE==0)? NDI/32 : KC2/32;

    float c[4][4][4];
#pragma unroll
    for(int a=0;a<4;a++)
#pragma unroll
        for(int b=0;b<4;b++)
#pragma unroll
            for(int q=0;q<4;q++) c[a][b][q]=0.f;

    // B loader (cp.async), both modes
    auto loadB = [&](int ci, int buf){
        int k0 = ci*32;
        for (int s=tid; s<1024; s+=256){
            int hl = s>>9, r = (s>>2)&127, seg = s&3;
            uint32_t dst = (hl? sBL : sBH) + ((buf*128+r)*LDT + seg*8)*2;
            const bf* src = (MODE==0)
                ? ((hl? g_WkL : g_WkH) + (size_t)(n0+r)*NDI + k0 + seg*8)
                : ((hl? g_WcL : g_WcH) + (size_t)(n0+r)*KC2 + k0 + seg*8);
            cpa16(dst, src);
        }
    };
    // A loader MODE0 (cp.async + gather)
    auto loadA0 = [&](int ci, int buf){
        int k0 = ci*32;
        for (int s=tid; s<1024; s+=256){
            int hl = s>>9, r = (s>>2)&127, seg = s&3;
            uint32_t dst = (hl? sAL : sAH) + ((buf*128+r)*LDT + seg*8)*2;
            int id = ids[(m0+r)*NNODE + (k0>>7)];
            const bf* src = (hl? g_embL : g_embH) + (size_t)id*DD + (k0&127) + seg*8;
            cpa16(dst, src);
        }
    };
    // A MODE1: regs load (LDG) then STS
    float4 ra[4]; float rl = 0.f;
    auto loadA1 = [&](int ci){
        int k0 = ci*32;
        int k = k0/384, hb = k0 - k*384;
        int m = m0 + (tid>>1);
        int t = m>>8, b = m&255;
        int s = t - (CSS-1) + k;
        if (s >= 0){
            rl = g_ld[(size_t)m*CSS + k];
            const float4* src = reinterpret_cast<const float4*>(
                g_hs + ((size_t)s*BB + b)*HH + hb + (tid&1)*16);
#pragma unroll
            for(int q=0;q<4;q++) ra[q] = src[q];
        } else {
            rl = 0.f;
#pragma unroll
            for(int q=0;q<4;q++) ra[q] = make_float4(0.f,0.f,0.f,0.f);
        }
    };
    auto storeA1 = [&](int buf){
        int r = tid>>1, hf = tid&1;
        unsigned ph[8], pl[8];
        const float* f = reinterpret_cast<const float*>(ra);
#pragma unroll
        for(int q=0;q<8;q++){
            bf h0,l0,h1,l1;
            bsplit(f[2*q+0]*rl, h0, l0);
            bsplit(f[2*q+1]*rl, h1, l1);
            ph[q] = (unsigned)__bfloat16_as_ushort(h0) | ((unsigned)__bfloat16_as_ushort(h1)<<16);
            pl[q] = (unsigned)__bfloat16_as_ushort(l0) | ((unsigned)__bfloat16_as_ushort(l1)<<16);
        }
        uint4* dh = reinterpret_cast<uint4*>(AsH + (buf*128+r)*LDT + hf*16);
        uint4* dl = reinterpret_cast<uint4*>(AsL + (buf*128+r)*LDT + hf*16);
        dh[0] = make_uint4(ph[0],ph[1],ph[2],ph[3]);
        dh[1] = make_uint4(ph[4],ph[5],ph[6],ph[7]);
        dl[0] = make_uint4(pl[0],pl[1],pl[2],pl[3]);
        dl[1] = make_uint4(pl[4],pl[5],pl[6],pl[7]);
    };

    // prologue: chunk 0
    if (MODE==1){ loadA1(0); storeA1(0); } else loadA0(0,0);
    loadB(0,0);
    asm volatile("cp.async.commit_group;");

    for (int ci=0; ci<KCH; ci++){
        int cur = ci & 1, nxt = cur ^ 1;
        if (ci+1 < KCH){
            if (MODE==1) loadA1(ci+1);      // LDG in flight
            else loadA0(ci+1, nxt);
            loadB(ci+1, nxt);
            asm volatile("cp.async.commit_group;");
            asm volatile("cp.async.wait_group 1;");
        } else {
            asm volatile("cp.async.wait_group 0;");
        }
        __syncthreads();

        const bf* aH = AsH + cur*128*LDT;
        const bf* aL = AsL + cur*128*LDT;
        const bf* bH = BsH + cur*128*LDT;
        const bf* bL = BsL + cur*128*LDT;
#pragma unroll
        for (int ks=0; ks<32; ks+=16){
            unsigned ah[4][4], al[4][4], bb[2][4];
            int arow = wm*64 + (lane&15), acol = ks + ((lane>>4)<<3);
            int brow = wn*32 + ((lane>>4)<<3) + (lane&7), bcol = ks + (((lane>>3)&1)<<3);
#pragma unroll
            for(int mi=0;mi<4;mi++) ldsm4(ah[mi], aH + (arow+mi*16)*LDT + acol);
#pragma unroll
            for(int gi=0;gi<2;gi++) ldsm4(bb[gi], bH + (brow+gi*16)*LDT + bcol);
#pragma unroll
            for(int mi=0;mi<4;mi++)
#pragma unroll
                for(int ni=0;ni<4;ni++)
                    mma16816(c[mi][ni], ah[mi], bb[ni>>1][(ni&1)*2], bb[ni>>1][(ni&1)*2+1]);
#pragma unroll
            for(int mi=0;mi<4;mi++) ldsm4(al[mi], aL + (arow+mi*16)*LDT + acol);
#pragma unroll
            for(int mi=0;mi<4;mi++)
#pragma unroll
                for(int ni=0;ni<4;ni++)
                    mma16816(c[mi][ni], al[mi], bb[ni>>1][(ni&1)*2], bb[ni>>1][(ni&1)*2+1]);
#pragma unroll
            for(int gi=0;gi<2;gi++) ldsm4(bb[gi], bL + (brow+gi*16)*LDT + bcol);
#pragma unroll
            for(int mi=0;mi<4;mi++)
#pragma unroll
                for(int ni=0;ni<4;ni++)
                    mma16816(c[mi][ni], ah[mi], bb[ni>>1][(ni&1)*2], bb[ni>>1][(ni&1)*2+1]);
        }
        if (MODE==1 && ci+1 < KCH) storeA1(nxt);
        __syncthreads();    // protect cur buffer from next iteration's loads; order storeA1
    }

    // epilogue
#pragma unroll
    for(int mi=0;mi<4;mi++){
#pragma unroll
        for(int hf=0; hf<2; hf++){
            int r = m0 + wm*64 + mi*16 + (lane>>2) + hf*8;
#pragma unroll
            for(int ni=0;ni<4;ni++){
                int n = n0 + wn*32 + ni*8 + ((lane&3)<<1);
                float v0 = c[mi][ni][hf*2+0], v1 = c[mi][ni][hf*2+1];
                if (MODE==0){
                    int b = r/VV, v = r%VV;
                    float tval = tv[r];
                    size_t base = ((size_t)v*BB + b)*GG;
                    if (n < GG)   g_XO[base+n]   = v0 + g_bias[n]   + tval*g_WsumT[n];
                    if (n+1 < GG) g_XO[base+n+1] = v1 + g_bias[n+1] + tval*g_WsumT[n+1];
                } else {
                    int t = r>>8, b = r&255;
                    size_t tb = (size_t)r*HH + n;
                    float o0 = g_theme[tb]  *(v0 + cb[n])   + g_hs[tb];
                    float o1 = g_theme[tb+1]*(v1 + cb[n+1]) + g_hs[tb+1];
                    size_t ob = ((size_t)b*VV + t)*HH + n;
                    g_rnn[ob]   = o0;
                    g_rnn[ob+1] = o1;
                }
            }
        }
    }
}

// ---------------- fp32 64x64 NT tile helper ----------------
__device__ __forceinline__ void gemm64(const float* __restrict__ A, int lda,
                                       const float* __restrict__ Bm, int ldb,
                                       int K, int brows, float (&acc)[4][4],
                                       float* As, float* Bs)
{
    int tid=threadIdx.x, lrow=tid>>2, lcol=(tid&3)<<2, trow=tid>>4, tcol=tid&15;
    for (int k0=0;k0<K;k0+=16){
        float4 a4 = *reinterpret_cast<const float4*>(A + (size_t)lrow*lda + k0 + lcol);
        float4 b4 = make_float4(0.f,0.f,0.f,0.f);
        if (lrow < brows) b4 = *reinterpret_cast<const float4*>(Bm + (size_t)lrow*ldb + k0 + lcol);
        As[(lcol+0)*64+lrow]=a4.x; As[(lcol+1)*64+lrow]=a4.y;
        As[(lcol+2)*64+lrow]=a4.z; As[(lcol+3)*64+lrow]=a4.w;
        Bs[(lcol+0)*64+lrow]=b4.x; Bs[(lcol+1)*64+lrow]=b4.y;
        Bs[(lcol+2)*64+lrow]=b4.z; Bs[(lcol+3)*64+lrow]=b4.w;
        __syncthreads();
#pragma unroll
        for (int p=0;p<16;p++){
            float ar[4], br[4];
#pragma unroll
            for(int i=0;i<4;i++) ar[i]=As[p*64+trow*4+i];
#pragma unroll
            for(int j=0;j<4;j++) br[j]=Bs[p*64+tcol*4+j];
#pragma unroll
            for(int i=0;i<4;i++)
#pragma unroll
                for(int j=0;j<4;j++) acc[i][j]=fmaf(ar[i],br[j],acc[i][j]);
        }
        __syncthreads();
    }
}

// ---------------- persistent recurrence ----------------
__device__ __forceinline__ void gridBarrier()
{
    __syncthreads();
    if (threadIdx.x==0){
        __threadfence();
        volatile unsigned* genp = &g_barGen;
        unsigned gen = *genp;
        if (atomicAdd(&g_barCount,1u) == NBLK-1){
            atomicExch(&g_barCount,0u);
            __threadfence();
            *genp = gen+1;
        } else {
            while (*genp == gen) __nanosleep(32);
        }
        __threadfence();
    }
    __syncthreads();
}

__global__ void __launch_bounds__(256) k_recur()
{
    __shared__ float As[16*64], Bs[16*64];
    __shared__ float sfm[LL], sim[LL];
    const int bid=blockIdx.x, tid=threadIdx.x;
    const int g0=(bid%25)*64, b0=(bid/25)*64;
    int brows = GG-g0; if (brows>64) brows=64;

    for (int t=0;t<VV;t++){
        {
            float acc[4][4] = {};
            gemm64(g_h + (size_t)b0*HH, HH, g_Wr + (size_t)g0*HH, HH, HH, brows, acc, As, Bs);
            int trow=tid>>4, tcol=tid&15;
#pragma unroll
            for(int i=0;i<4;i++){
                int b=b0+trow*4+i;
#pragma unroll
                for(int j=0;j<4;j++){
                    int g=g0+tcol*4+j;
                    if (g<GG) g_xobuf[b*GG+g] = acc[i][j] + g_XO[((size_t)t*BB+b)*GG+g];
                }
            }
        }
        gridBarrier();
        for (int b=bid; b<BB; b+=NBLK){
            const float* xo = g_xobuf + b*GG;
            if (tid==0){
                float v[LL], mx=-1e30f;
#pragma unroll
                for(int i=0;i<LL;i++){ v[i]=xo[i]; mx=fmaxf(mx,v[i]); }
                float s=0.f;
#pragma unroll
                for(int i=0;i<LL;i++){ v[i]=expf(v[i]-mx); s+=v[i]; }
                float inv=1.f/s, run=0.f, fsum=0.f;
#pragma unroll
                for(int i=0;i<LL;i++){ run+=v[i]*inv; sfm[i]=run; fsum+=run; }
                g_dists[t*BB+b] = 1.f - fsum/(float)LL;
            } else if (tid==32){
                float v[LL], mx=-1e30f;
#pragma unroll
                for(int i=0;i<LL;i++){ v[i]=xo[LL+i]; mx=fmaxf(mx,v[i]); }
                float s=0.f;
#pragma unroll
                for(int i=0;i<LL;i++){ v[i]=expf(v[i]-mx); s+=v[i]; }
                float inv=1.f/s, run=0.f;
#pragma unroll
                for(int i=LL-1;i>=0;i--){ run+=v[i]*inv; sim[i]=run; }
            }
            __syncthreads();
#pragma unroll
            for(int r=0;r<2;r++){
                int hh = tid + r*256;
                if (hh < HH){
                    int l = hh>>5;
                    float fg = sigmoidf(xo[24+hh]);
                    float ig = sigmoidf(xo[24+384+hh]);
                    float og = sigmoidf(xo[24+768+hh]);
                    float ci = tanhf(xo[24+1152+hh]);
                    float fmv=sfm[l], imv=sim[l], ov=fmv*imv;
                    float cold = g_c[b*HH+hh];
                    float cn = ov*(fg*cold+ig*ci) + (fmv-ov)*cold + (imv-ov)*ci;
                    float hv = og*tanhf(cn);
                    g_c[b*HH+hh]=cn; g_h[b*HH+hh]=hv;
                    g_hs[((size_t)t*BB+b)*HH+hh]=hv;
                }
            }
            __syncthreads();
        }
        gridBarrier();
    }
}

// ---------------- ld weights ----------------
__global__ void k_ld()
{
    int idx = blockIdx.x*256 + threadIdx.x;
    int t = idx/BB, b = idx%BB;
    float cum[CSS], run=0.f;
#pragma unroll
    for(int k=0;k<CSS;k++){
        int s = t-(CSS-1)+k;
        run += (s>=0)? g_dists[s*BB+b] : 0.f;
        cum[k]=run;
    }
    float mx=cum[0];
#pragma unroll
    for(int k=1;k<CSS;k++) mx=fmaxf(mx,cum[k]);
    float e[CSS], s=0.f;
#pragma unroll
    for(int k=0;k<CSS;k++){ e[k]=expf(cum[k]-mx); s+=e[k]; }
    float inv=1.f/s;
#pragma unroll
    for(int k=0;k<CSS;k++) g_ld[(size_t)idx*CSS+k]=e[k]*inv;
}

// ---------------- mh = mean_k ld*hs ----------------
__global__ void k_mh()
{
    long idx = (long)blockIdx.x*256 + threadIdx.x;
    int t = (int)(idx/(BB*HH));
    int r = (int)(idx%(BB*HH));
    int b = r/HH, h = r%HH;
    const float* ld = g_ld + ((size_t)t*BB+b)*CSS;
    float s=0.f;
#pragma unroll
    for(int k=0;k<CSS;k++){
        int sv = t-(CSS-1)+k;
        if (sv>=0) s += ld[k]*g_hs[((size_t)sv*BB+b)*HH+h];
    }
    g_mh[idx] = s*0.1f;
}

// ---------------- theme MLP ----------------
__global__ void __launch_bounds__(256) k_theme1(const float* __restrict__ sw, const float* __restrict__ sb)
{
    __shared__ float As[16*64], Bs[16*64];
    int m0 = blockIdx.y*64;
    float acc[4][4] = {};
    gemm64(g_mh + (size_t)m0*HH, HH, sw, HH, HH, 64, acc, As, Bs);
    int trow=threadIdx.x>>4, tcol=threadIdx.x&15;
#pragma unroll
    for(int i=0;i<4;i++){
        int m=m0+trow*4+i;
#pragma unroll
        for(int j=0;j<4;j++){
            int n=tcol*4+j;
            g_hid[(size_t)m*HSS+n] = fmaxf(acc[i][j]+sb[n], 0.f);
        }
    }
}
__global__ void __launch_bounds__(256) k_theme2(const float* __restrict__ rsw, const float* __restrict__ rsb)
{
    __shared__ float As[16*64], Bs[16*64];
    int n0 = blockIdx.x*64, m0 = blockIdx.y*64;
    float acc[4][4] = {};
    gemm64(g_hid + (size_t)m0*HSS, HSS, rsw + (size_t)n0*HSS, HSS, HSS, 64, acc, As, Bs);
    int trow=threadIdx.x>>4, tcol=threadIdx.x&15;
#pragma unroll
    for(int i=0;i<4;i++){
        int m=m0+trow*4+i;
#pragma unroll
        for(int j=0;j<4;j++){
            int n=n0+tcol*4+j;
            g_theme[(size_t)m*HH+n] = sigmoidf(acc[i][j]+rsb[n]);
        }
    }
}

// ---------------- out GEMM (split-K) + reduce ----------------
__global__ void __launch_bounds__(256) k_out(const float* __restrict__ ow)
{
    __shared__ float As[16*64], Bs[16*64];
    int n0=blockIdx.x*64, m0=blockIdx.y*64, z=blockIdx.z;
    float acc[4][4] = {};
    gemm64(g_rnn + (size_t)m0*(VV*HH) + z*1200, VV*HH,
           ow + (size_t)n0*(VV*HH) + z*1200, VV*HH, 1200, 64, acc, As, Bs);
    int trow=threadIdx.x>>4, tcol=threadIdx.x&15;
#pragma unroll
    for(int i=0;i<4;i++){
        int m=m0+trow*4+i;
#pragma unroll
        for(int j=0;j<4;j++){
            int n=n0+tcol*4+j;
            g_outPart[((size_t)z*BB+m)*OUTT+n]=acc[i][j];
        }
    }
}
__global__ void k_reduce(const float* __restrict__ out_b, float* __restrict__ outp, int total)
{
    int idx = blockIdx.x*256 + threadIdx.x;
    if (idx >= total) return;
    if (idx < BB*OUTT){
        float s = out_b[idx & (OUTT-1)];
#pragma unroll
        for(int z=0;z<16;z++) s += g_outPart[(size_t)z*(BB*OUTT)+idx];
        outp[idx]=s;
    } else if (idx < BB*OUTT + VV*BB){
        outp[idx] = g_dists[idx - BB*OUTT];
    }
}

// ---------------- launch ----------------
extern "C" void kernel_launch(void* const* d_in, const int* in_sizes, int n_in,
                              void* d_out, int out_size)
{
    const int*   node_ids  = (const int*)d_in[0];
    const float* timev     = (const float*)d_in[3];
    const float* embed     = (const float*)d_in[6];
    const float* kernel_w  = (const float*)d_in[7];
    const float* kernel_b  = (const float*)d_in[8];
    const float* rec_w     = (const float*)d_in[9];
    const float* rec_b     = (const float*)d_in[10];
    const float* scale_w   = (const float*)d_in[11];
    const float* scale_b   = (const float*)d_in[12];
    const float* rescale_w = (const float*)d_in[13];
    const float* rescale_b = (const float*)d_in[14];
    const float* conv_w    = (const float*)d_in[15];
    const float* conv_b    = (const float*)d_in[16];
    const float* out_w     = (const float*)d_in[17];
    const float* out_b     = (const float*)d_in[18];
    float* outp = (float*)d_out;

    const int SMEM = 2*128*LDT*2*4;   // 81920 bytes
    static bool cfg = false;
    if (!cfg){
        cudaFuncSetAttribute(k_gma<0>, cudaFuncAttributeMaxDynamicSharedMemorySize, SMEM);
        cudaFuncSetAttribute(k_gma<1>, cudaFuncAttributeMaxDynamicSharedMemorySize, SMEM);
        cfg = true;
    }

    long prep_total = (long)GPAD*NDI + 10001L*DD + (long)HH*KC2 + GG + (long)GG*HH + 2L*BB*HH + 1;
    k_prep<<<(int)((prep_total+255)/256), 256>>>(kernel_w, rec_w, conv_w, kernel_b, rec_b, embed);

    k_gma<0><<<dim3(13,100), 256, SMEM>>>(node_ids, timev, conv_b);
    k_recur<<<NBLK, 256>>>();
    k_ld<<<50, 256>>>();
    k_mh<<<19200, 256>>>();
    k_theme1<<<dim3(1,200), 256>>>(scale_w, scale_b);
    k_theme2<<<dim3(6,200), 256>>>(rescale_w, rescale_b);
    k_gma<1><<<dim3(3,100), 256, SMEM>>>(node_ids, timev, conv_b);
    k_out<<<dim3(2,4,16), 256>>>(out_w);
    k_reduce<<<(out_size+255)/256, 256>>>(out_b, outp, out_size);
}

// round 6
// speedup vs baseline: 1.9485x; 1.1247x over previous
#include <cuda_runtime.h>
#include <cuda_bf16.h>
#include <cstdint>

#define BB 256
#define VV 50
#define NNODE 32
#define DD 128
#define NDI 4096
#define HH 384
#define LL 12
#define CSS 10
#define GG 1560
#define GPAD 1792
#define GP2 2048
#define HSS 64
#define OUTT 128
#define KC2 3840
#define LDT 40

typedef __nv_bfloat16 bf;

__device__ bf g_WkH[(size_t)GPAD*NDI], g_WkL[(size_t)GPAD*NDI];
__device__ bf g_embH[10001*DD], g_embL[10001*DD];
__device__ bf g_WcH[(size_t)HH*KC2], g_WcL[(size_t)HH*KC2];
__device__ bf g_WrH[(size_t)GP2*HH], g_WrL[(size_t)GP2*HH];
__device__ bf g_hH[BB*HH], g_hL[BB*HH];
__device__ float g_bias[GG], g_WsumT[GG];
__device__ float g_XO[(size_t)VV*BB*GG];
__device__ float g_xobuf[BB*GG];
__device__ float g_c[BB*HH];
__device__ float g_hs[(size_t)VV*BB*HH];
__device__ float g_dists[VV*BB];
__device__ float g_ld[VV*BB*CSS];
__device__ float g_mh[(size_t)VV*BB*HH];
__device__ float g_hid[(size_t)VV*BB*HSS];
__device__ float g_theme[(size_t)VV*BB*HH];
__device__ float g_rnn[(size_t)BB*VV*HH];
__device__ float g_outPart[16*BB*OUTT];

__device__ __forceinline__ float sigmoidf(float x){ return 1.f/(1.f+expf(-x)); }
__device__ __forceinline__ void bsplit(float v, bf& hi, bf& lo){
    bf h = __float2bfloat16(v); hi = h; lo = __float2bfloat16(v - __bfloat162float(h));
}
__device__ __forceinline__ void cpa16(uint32_t dst, const void* src){
    asm volatile("cp.async.cg.shared.global [%0], [%1], 16;" :: "r"(dst), "l"(src));
}
__device__ __forceinline__ void ldsm4(unsigned* r, const bf* p){
    unsigned a = (unsigned)__cvta_generic_to_shared(p);
    asm volatile("ldmatrix.sync.aligned.m8n8.x4.shared.b16 {%0,%1,%2,%3}, [%4];"
        : "=r"(r[0]),"=r"(r[1]),"=r"(r[2]),"=r"(r[3]) : "r"(a));
}
__device__ __forceinline__ void mma16816(float* c, const unsigned* a, unsigned b0, unsigned b1){
    asm volatile("mma.sync.aligned.m16n8k16.row.col.f32.bf16.bf16.f32 "
        "{%0,%1,%2,%3}, {%4,%5,%6,%7}, {%8,%9}, {%0,%1,%2,%3};"
        : "+f"(c[0]),"+f"(c[1]),"+f"(c[2]),"+f"(c[3])
        : "r"(a[0]),"r"(a[1]),"r"(a[2]),"r"(a[3]), "r"(b0),"r"(b1));
}

// ---------------- prep ----------------
__global__ void k_prep(const float* __restrict__ kw, const float* __restrict__ rw,
                       const float* __restrict__ cw, const float* __restrict__ kb,
                       const float* __restrict__ rb, const float* __restrict__ em)
{
    const long R1=(long)GPAD*NDI, R2=10001L*DD, R3=(long)HH*KC2, R4=GG, R5=(long)GP2*HH, R6=(long)BB*HH;
    long i = (long)blockIdx.x*256 + threadIdx.x;
    if (i < R1){ long g=i/NDI,k=i%NDI; float v=(g<GG)?kw[g*4097+k]:0.f; bsplit(v,g_WkH[i],g_WkL[i]); return; }
    i-=R1;
    if (i < R2){ bsplit(em[i],g_embH[i],g_embL[i]); return; }
    i-=R2;
    if (i < R3){ long o=i/KC2, c=i%KC2; long k=c/HH, h=c%HH;
        bsplit(cw[(o*HH+h)*CSS+k], g_WcH[i], g_WcL[i]); return; }
    i-=R3;
    if (i < R4){ g_bias[i]=kb[i]+rb[i]; g_WsumT[i]=kw[i*4097+4096]+rw[i*385+384]; return; }
    i-=R4;
    if (i < R5){ long g=i/HH,j=i%HH; float v=(g<GG)? rw[g*385+j] : 0.f;
        bsplit(v, g_WrH[i], g_WrL[i]); return; }
    i-=R5;
    if (i < R6){ g_c[i]=0.f; g_hH[i]=__float2bfloat16(0.f); g_hL[i]=__float2bfloat16(0.f); }
}

// -------- mma.sync split-3 bf16 GEMM: C(128x128) = A(128xK) * B(128xK)^T --------
// MODE 0: A = gathered embeddings (m=b*50+v), B = Wk,  K=4096, epi -> g_XO
// MODE 1: A = ld*hs built on the fly (m=t*256+b), B = Wc, K=3840, epi -> g_rnn
template<int MODE>
__global__ void __launch_bounds__(256,2) k_gma(const int* __restrict__ ids,
    const float* __restrict__ tv, const float* __restrict__ cb)
{
    extern __shared__ __align__(16) bf smem[];
    bf* AsH = smem;
    bf* AsL = AsH + 2*128*LDT;
    bf* BsH = AsL + 2*128*LDT;
    bf* BsL = BsH + 2*128*LDT;
    uint32_t sAH = (uint32_t)__cvta_generic_to_shared(AsH);
    uint32_t sAL = (uint32_t)__cvta_generic_to_shared(AsL);
    uint32_t sBH = (uint32_t)__cvta_generic_to_shared(BsH);
    uint32_t sBL = (uint32_t)__cvta_generic_to_shared(BsL);
    const int tid = threadIdx.x, lane = tid&31, w = tid>>5;
    const int wm = w>>2, wn = w&3;
    const int m0 = blockIdx.y*128, n0 = blockIdx.x*128;
    const int KCH = (MODE==0)? NDI/32 : KC2/32;

    float c[4][4][4];
#pragma unroll
    for(int a=0;a<4;a++)
#pragma unroll
        for(int b=0;b<4;b++)
#pragma unroll
            for(int q=0;q<4;q++) c[a][b][q]=0.f;

    auto loadB = [&](int ci, int buf){
        int k0 = ci*32;
        for (int s=tid; s<1024; s+=256){
            int hl = s>>9, r = (s>>2)&127, seg = s&3;
            uint32_t dst = (hl? sBL : sBH) + ((buf*128+r)*LDT + seg*8)*2;
            const bf* src = (MODE==0)
                ? ((hl? g_WkL : g_WkH) + (size_t)(n0+r)*NDI + k0 + seg*8)
                : ((hl? g_WcL : g_WcH) + (size_t)(n0+r)*KC2 + k0 + seg*8);
            cpa16(dst, src);
        }
    };
    auto loadA0 = [&](int ci, int buf){
        int k0 = ci*32;
        for (int s=tid; s<1024; s+=256){
            int hl = s>>9, r = (s>>2)&127, seg = s&3;
            uint32_t dst = (hl? sAL : sAH) + ((buf*128+r)*LDT + seg*8)*2;
            int id = ids[(m0+r)*NNODE + (k0>>7)];
            const bf* src = (hl? g_embL : g_embH) + (size_t)id*DD + (k0&127) + seg*8;
            cpa16(dst, src);
        }
    };
    float4 ra[4]; float rl = 0.f;
    auto loadA1 = [&](int ci){
        int k0 = ci*32;
        int k = k0/384, hb = k0 - k*384;
        int m = m0 + (tid>>1);
        int t = m>>8, b = m&255;
        int s = t - (CSS-1) + k;
        if (s >= 0){
            rl = g_ld[(size_t)m*CSS + k];
            const float4* src = reinterpret_cast<const float4*>(
                g_hs + ((size_t)s*BB + b)*HH + hb + (tid&1)*16);
#pragma unroll
            for(int q=0;q<4;q++) ra[q] = src[q];
        } else {
            rl = 0.f;
#pragma unroll
            for(int q=0;q<4;q++) ra[q] = make_float4(0.f,0.f,0.f,0.f);
        }
    };
    auto storeA1 = [&](int buf){
        int r = tid>>1, hf = tid&1;
        unsigned ph[8], pl[8];
        const float* f = reinterpret_cast<const float*>(ra);
#pragma unroll
        for(int q=0;q<8;q++){
            bf h0,l0,h1,l1;
            bsplit(f[2*q+0]*rl, h0, l0);
            bsplit(f[2*q+1]*rl, h1, l1);
            ph[q] = (unsigned)__bfloat16_as_ushort(h0) | ((unsigned)__bfloat16_as_ushort(h1)<<16);
            pl[q] = (unsigned)__bfloat16_as_ushort(l0) | ((unsigned)__bfloat16_as_ushort(l1)<<16);
        }
        uint4* dh = reinterpret_cast<uint4*>(AsH + (buf*128+r)*LDT + hf*16);
        uint4* dl = reinterpret_cast<uint4*>(AsL + (buf*128+r)*LDT + hf*16);
        dh[0] = make_uint4(ph[0],ph[1],ph[2],ph[3]);
        dh[1] = make_uint4(ph[4],ph[5],ph[6],ph[7]);
        dl[0] = make_uint4(pl[0],pl[1],pl[2],pl[3]);
        dl[1] = make_uint4(pl[4],pl[5],pl[6],pl[7]);
    };

    if (MODE==1){ loadA1(0); storeA1(0); } else loadA0(0,0);
    loadB(0,0);
    asm volatile("cp.async.commit_group;");

    for (int ci=0; ci<KCH; ci++){
        int cur = ci & 1, nxt = cur ^ 1;
        if (ci+1 < KCH){
            if (MODE==1) loadA1(ci+1);
            else loadA0(ci+1, nxt);
            loadB(ci+1, nxt);
            asm volatile("cp.async.commit_group;");
            asm volatile("cp.async.wait_group 1;");
        } else {
            asm volatile("cp.async.wait_group 0;");
        }
        __syncthreads();

        const bf* aH = AsH + cur*128*LDT;
        const bf* aL = AsL + cur*128*LDT;
        const bf* bH = BsH + cur*128*LDT;
        const bf* bL = BsL + cur*128*LDT;
#pragma unroll
        for (int ks=0; ks<32; ks+=16){
            unsigned ah[4][4], al[4][4], bb[2][4];
            int arow = wm*64 + (lane&15), acol = ks + ((lane>>4)<<3);
            int brow = wn*32 + ((lane>>4)<<3) + (lane&7), bcol = ks + (((lane>>3)&1)<<3);
#pragma unroll
            for(int mi=0;mi<4;mi++) ldsm4(ah[mi], aH + (arow+mi*16)*LDT + acol);
#pragma unroll
            for(int gi=0;gi<2;gi++) ldsm4(bb[gi], bH + (brow+gi*16)*LDT + bcol);
#pragma unroll
            for(int mi=0;mi<4;mi++)
#pragma unroll
                for(int ni=0;ni<4;ni++)
                    mma16816(c[mi][ni], ah[mi], bb[ni>>1][(ni&1)*2], bb[ni>>1][(ni&1)*2+1]);
#pragma unroll
            for(int mi=0;mi<4;mi++) ldsm4(al[mi], aL + (arow+mi*16)*LDT + acol);
#pragma unroll
            for(int mi=0;mi<4;mi++)
#pragma unroll
                for(int ni=0;ni<4;ni++)
                    mma16816(c[mi][ni], al[mi], bb[ni>>1][(ni&1)*2], bb[ni>>1][(ni&1)*2+1]);
#pragma unroll
            for(int gi=0;gi<2;gi++) ldsm4(bb[gi], bL + (brow+gi*16)*LDT + bcol);
#pragma unroll
            for(int mi=0;mi<4;mi++)
#pragma unroll
                for(int ni=0;ni<4;ni++)
                    mma16816(c[mi][ni], ah[mi], bb[ni>>1][(ni&1)*2], bb[ni>>1][(ni&1)*2+1]);
        }
        if (MODE==1 && ci+1 < KCH) storeA1(nxt);
        __syncthreads();
    }

#pragma unroll
    for(int mi=0;mi<4;mi++){
#pragma unroll
        for(int hf=0; hf<2; hf++){
            int r = m0 + wm*64 + mi*16 + (lane>>2) + hf*8;
#pragma unroll
            for(int ni=0;ni<4;ni++){
                int n = n0 + wn*32 + ni*8 + ((lane&3)<<1);
                float v0 = c[mi][ni][hf*2+0], v1 = c[mi][ni][hf*2+1];
                if (MODE==0){
                    int b = r/VV, v = r%VV;
                    float tval = tv[r];
                    size_t base = ((size_t)v*BB + b)*GG;
                    if (n < GG)   g_XO[base+n]   = v0 + g_bias[n]   + tval*g_WsumT[n];
                    if (n+1 < GG) g_XO[base+n+1] = v1 + g_bias[n+1] + tval*g_WsumT[n+1];
                } else {
                    int t = r>>8, b = r&255;
                    size_t tb = (size_t)r*HH + n;
                    float o0 = g_theme[tb]  *(v0 + cb[n])   + g_hs[tb];
                    float o1 = g_theme[tb+1]*(v1 + cb[n+1]) + g_hs[tb+1];
                    size_t ob = ((size_t)b*VV + t)*HH + n;
                    g_rnn[ob]   = o0;
                    g_rnn[ob+1] = o1;
                }
            }
        }
    }
}

// ---------------- persistent recurrence: 8 b-groups x cluster-of-8 g-slices ----------------
// CTA: bgroup = blockIdx.x>>3 (32 b rows), rank = blockIdx.x&7 (g-slice of 256, padded GP2=2048)
// Phase A (tensorized): xo[32b x 256g] = h @ Wr_slice^T (split-3 bf16) + XO[t]
// Phase B: gates for 4 b per CTA. Sync via barrier.cluster (scope = one b-group).
__global__ void __launch_bounds__(256) __cluster_dims__(8,1,1) k_recur()
{
    extern __shared__ __align__(16) bf rsm[];
    bf* hHs = rsm;                    // 32*392
    bf* hLs = hHs + 32*392;
    bf* wHs = hLs + 32*392;           // 2 bufs * 256*LDT
    bf* wLs = wHs + 2*256*LDT;
    uint32_t shH = (uint32_t)__cvta_generic_to_shared(hHs);
    uint32_t shL = (uint32_t)__cvta_generic_to_shared(hLs);
    uint32_t swH = (uint32_t)__cvta_generic_to_shared(wHs);
    uint32_t swL = (uint32_t)__cvta_generic_to_shared(wLs);
    __shared__ float sfm[4][LL], sim[4][LL];

    const int tid = threadIdx.x, lane = tid&31, w = tid>>5;
    const int bgroup = blockIdx.x>>3, rank = blockIdx.x&7;
    const int bbase = bgroup*32;
    const int gg0 = rank*256;

    auto loadH = [&](){
        for (int s=tid; s<3072; s+=256){
            int hl = (s>=1536)?1:0, s2 = s - hl*1536;
            int r = s2/48, seg = s2%48;
            const bf* src = (hl? g_hL : g_hH) + (size_t)(bbase+r)*HH + seg*8;
            uint32_t dst = (hl? shL : shH) + (r*392 + seg*8)*2;
            cpa16(dst, src);
        }
    };
    auto loadW = [&](int ci, int buf){
        for (int s=tid; s<2048; s+=256){
            int hl = s>>10, r = (s&1023)>>2, seg = s&3;
            const bf* src = (hl? g_WrL : g_WrH) + (size_t)(gg0+r)*HH + ci*32 + seg*8;
            uint32_t dst = (hl? swL : swH) + ((buf*256+r)*LDT + seg*8)*2;
            cpa16(dst, src);
        }
    };

    for (int t=0; t<VV; t++){
        // ---- phase A ----
        float c[2][4][4];
#pragma unroll
        for(int a=0;a<2;a++)
#pragma unroll
            for(int b=0;b<4;b++)
#pragma unroll
                for(int q=0;q<4;q++) c[a][b][q]=0.f;

        loadH(); loadW(0,0);
        asm volatile("cp.async.commit_group;");
        asm volatile("cp.async.wait_group 0;");
        __syncthreads();

        for (int ci=0; ci<12; ci++){
            int cur = ci&1;
            if (ci+1 < 12){
                loadW(ci+1, cur^1);
                asm volatile("cp.async.commit_group;");
                asm volatile("cp.async.wait_group 1;");
            } else {
                asm volatile("cp.async.wait_group 0;");
            }
            __syncthreads();
#pragma unroll
            for (int ks=0; ks<32; ks+=16){
                unsigned ah[2][4], al[2][4], bb[2][4];
                int arow = lane&15, acol = ci*32 + ks + ((lane>>4)<<3);
                int brow = w*32 + ((lane>>4)<<3) + (lane&7), bcol = ks + (((lane>>3)&1)<<3);
#pragma unroll
                for(int mi=0;mi<2;mi++) ldsm4(ah[mi], hHs + (arow+mi*16)*392 + acol);
#pragma unroll
                for(int gi=0;gi<2;gi++) ldsm4(bb[gi], wHs + (cur*256+brow+gi*16)*LDT + bcol);
#pragma unroll
                for(int mi=0;mi<2;mi++)
#pragma unroll
                    for(int ni=0;ni<4;ni++)
                        mma16816(c[mi][ni], ah[mi], bb[ni>>1][(ni&1)*2], bb[ni>>1][(ni&1)*2+1]);
#pragma unroll
                for(int mi=0;mi<2;mi++) ldsm4(al[mi], hLs + (arow+mi*16)*392 + acol);
#pragma unroll
                for(int mi=0;mi<2;mi++)
#pragma unroll
                    for(int ni=0;ni<4;ni++)
                        mma16816(c[mi][ni], al[mi], bb[ni>>1][(ni&1)*2], bb[ni>>1][(ni&1)*2+1]);
#pragma unroll
                for(int gi=0;gi<2;gi++) ldsm4(bb[gi], wLs + (cur*256+brow+gi*16)*LDT + bcol);
#pragma unroll
                for(int mi=0;mi<2;mi++)
#pragma unroll
                    for(int ni=0;ni<4;ni++)
                        mma16816(c[mi][ni], ah[mi], bb[ni>>1][(ni&1)*2], bb[ni>>1][(ni&1)*2+1]);
            }
            __syncthreads();
        }

        // epilogue: xo = c + XO[t]
#pragma unroll
        for(int mi=0;mi<2;mi++){
#pragma unroll
            for(int hf=0; hf<2; hf++){
                int rloc = mi*16 + (lane>>2) + hf*8;
                int b = bbase + rloc;
                size_t xbase = ((size_t)t*BB + b)*GG;
#pragma unroll
                for(int ni=0;ni<4;ni++){
                    int g = gg0 + w*32 + ni*8 + ((lane&3)<<1);
                    if (g < GG)   g_xobuf[(size_t)b*GG+g]   = c[mi][ni][hf*2+0] + g_XO[xbase+g];
                    if (g+1 < GG) g_xobuf[(size_t)b*GG+g+1] = c[mi][ni][hf*2+1] + g_XO[xbase+g+1];
                }
            }
        }
        __threadfence();
        asm volatile("barrier.cluster.arrive.aligned;" ::: "memory");
        asm volatile("barrier.cluster.wait.aligned;" ::: "memory");

        // ---- phase B: 4 b per CTA ----
        {
            int b_local = w>>1, half = w&1;
            int b = bbase + rank*4 + b_local;
            const float* xo = g_xobuf + (size_t)b*GG;
            if (half==0 && lane==0){
                float v[LL], mx=-1e30f;
#pragma unroll
                for(int i=0;i<LL;i++){ v[i]=__ldcg(xo+i); mx=fmaxf(mx,v[i]); }
                float s=0.f;
#pragma unroll
                for(int i=0;i<LL;i++){ v[i]=expf(v[i]-mx); s+=v[i]; }
                float inv=1.f/s, run=0.f, fsum=0.f;
#pragma unroll
                for(int i=0;i<LL;i++){ run+=v[i]*inv; sfm[b_local][i]=run; fsum+=run; }
                g_dists[t*BB+b] = 1.f - fsum/(float)LL;
            } else if (half==0 && lane==16){
                float v[LL], mx=-1e30f;
#pragma unroll
                for(int i=0;i<LL;i++){ v[i]=__ldcg(xo+LL+i); mx=fmaxf(mx,v[i]); }
                float s=0.f;
#pragma unroll
                for(int i=0;i<LL;i++){ v[i]=expf(v[i]-mx); s+=v[i]; }
                float inv=1.f/s, run=0.f;
#pragma unroll
                for(int i=LL-1;i>=0;i--){ run+=v[i]*inv; sim[b_local][i]=run; }
            }
            __syncthreads();
#pragma unroll
            for(int r=0;r<6;r++){
                int hh = half*192 + r*32 + lane;
                int l = hh>>5;
                float fg = sigmoidf(__ldcg(xo+24+hh));
                float ig = sigmoidf(__ldcg(xo+24+384+hh));
                float og = sigmoidf(__ldcg(xo+24+768+hh));
                float ci = tanhf(__ldcg(xo+24+1152+hh));
                float fmv=sfm[b_local][l], imv=sim[b_local][l], ov=fmv*imv;
                float cold = g_c[b*HH+hh];
                float cn = ov*(fg*cold+ig*ci) + (fmv-ov)*cold + (imv-ov)*ci;
                float hv = og*tanhf(cn);
                g_c[b*HH+hh]=cn;
                bsplit(hv, g_hH[b*HH+hh], g_hL[b*HH+hh]);
                g_hs[((size_t)t*BB+b)*HH+hh]=hv;
            }
        }
        __threadfence();
        asm volatile("barrier.cluster.arrive.aligned;" ::: "memory");
        asm volatile("barrier.cluster.wait.aligned;" ::: "memory");
    }
}

// ---------------- fp32 64x64 NT tile helper ----------------
__device__ __forceinline__ void gemm64(const float* __restrict__ A, int lda,
                                       const float* __restrict__ Bm, int ldb,
                                       int K, int brows, float (&acc)[4][4],
                                       float* As, float* Bs)
{
    int tid=threadIdx.x, lrow=tid>>2, lcol=(tid&3)<<2, trow=tid>>4, tcol=tid&15;
    for (int k0=0;k0<K;k0+=16){
        float4 a4 = *reinterpret_cast<const float4*>(A + (size_t)lrow*lda + k0 + lcol);
        float4 b4 = make_float4(0.f,0.f,0.f,0.f);
        if (lrow < brows) b4 = *reinterpret_cast<const float4*>(Bm + (size_t)lrow*ldb + k0 + lcol);
        As[(lcol+0)*64+lrow]=a4.x; As[(lcol+1)*64+lrow]=a4.y;
        As[(lcol+2)*64+lrow]=a4.z; As[(lcol+3)*64+lrow]=a4.w;
        Bs[(lcol+0)*64+lrow]=b4.x; Bs[(lcol+1)*64+lrow]=b4.y;
        Bs[(lcol+2)*64+lrow]=b4.z; Bs[(lcol+3)*64+lrow]=b4.w;
        __syncthreads();
#pragma unroll
        for (int p=0;p<16;p++){
            float ar[4], br[4];
#pragma unroll
            for(int i=0;i<4;i++) ar[i]=As[p*64+trow*4+i];
#pragma unroll
            for(int j=0;j<4;j++) br[j]=Bs[p*64+tcol*4+j];
#pragma unroll
            for(int i=0;i<4;i++)
#pragma unroll
                for(int j=0;j<4;j++) acc[i][j]=fmaf(ar[i],br[j],acc[i][j]);
        }
        __syncthreads();
    }
}

// ---------------- ld weights ----------------
__global__ void k_ld()
{
    int idx = blockIdx.x*256 + threadIdx.x;
    int t = idx/BB, b = idx%BB;
    float cum[CSS], run=0.f;
#pragma unroll
    for(int k=0;k<CSS;k++){
        int s = t-(CSS-1)+k;
        run += (s>=0)? g_dists[s*BB+b] : 0.f;
        cum[k]=run;
    }
    float mx=cum[0];
#pragma unroll
    for(int k=1;k<CSS;k++) mx=fmaxf(mx,cum[k]);
    float e[CSS], s=0.f;
#pragma unroll
    for(int k=0;k<CSS;k++){ e[k]=expf(cum[k]-mx); s+=e[k]; }
    float inv=1.f/s;
#pragma unroll
    for(int k=0;k<CSS;k++) g_ld[(size_t)idx*CSS+k]=e[k]*inv;
}

// ---------------- mh = mean_k ld*hs ----------------
__global__ void k_mh()
{
    long idx = (long)blockIdx.x*256 + threadIdx.x;
    int t = (int)(idx/(BB*HH));
    int r = (int)(idx%(BB*HH));
    int b = r/HH, h = r%HH;
    const float* ld = g_ld + ((size_t)t*BB+b)*CSS;
    float s=0.f;
#pragma unroll
    for(int k=0;k<CSS;k++){
        int sv = t-(CSS-1)+k;
        if (sv>=0) s += ld[k]*g_hs[((size_t)sv*BB+b)*HH+h];
    }
    g_mh[idx] = s*0.1f;
}

// ---------------- theme MLP ----------------
__global__ void __launch_bounds__(256) k_theme1(const float* __restrict__ sw, const float* __restrict__ sb)
{
    __shared__ float As[16*64], Bs[16*64];
    int m0 = blockIdx.y*64;
    float acc[4][4] = {};
    gemm64(g_mh + (size_t)m0*HH, HH, sw, HH, HH, 64, acc, As, Bs);
    int trow=threadIdx.x>>4, tcol=threadIdx.x&15;
#pragma unroll
    for(int i=0;i<4;i++){
        int m=m0+trow*4+i;
#pragma unroll
        for(int j=0;j<4;j++){
            int n=tcol*4+j;
            g_hid[(size_t)m*HSS+n] = fmaxf(acc[i][j]+sb[n], 0.f);
        }
    }
}
__global__ void __launch_bounds__(256) k_theme2(const float* __restrict__ rsw, const float* __restrict__ rsb)
{
    __shared__ float As[16*64], Bs[16*64];
    int n0 = blockIdx.x*64, m0 = blockIdx.y*64;
    float acc[4][4] = {};
    gemm64(g_hid + (size_t)m0*HSS, HSS, rsw + (size_t)n0*HSS, HSS, HSS, 64, acc, As, Bs);
    int trow=threadIdx.x>>4, tcol=threadIdx.x&15;
#pragma unroll
    for(int i=0;i<4;i++){
        int m=m0+trow*4+i;
#pragma unroll
        for(int j=0;j<4;j++){
            int n=n0+tcol*4+j;
            g_theme[(size_t)m*HH+n] = sigmoidf(acc[i][j]+rsb[n]);
        }
    }
}

// ---------------- out GEMM (split-K) + reduce ----------------
__global__ void __launch_bounds__(256) k_out(const float* __restrict__ ow)
{
    __shared__ float As[16*64], Bs[16*64];
    int n0=blockIdx.x*64, m0=blockIdx.y*64, z=blockIdx.z;
    float acc[4][4] = {};
    gemm64(g_rnn + (size_t)m0*(VV*HH) + z*1200, VV*HH,
           ow + (size_t)n0*(VV*HH) + z*1200, VV*HH, 1200, 64, acc, As, Bs);
    int trow=threadIdx.x>>4, tcol=threadIdx.x&15;
#pragma unroll
    for(int i=0;i<4;i++){
        int m=m0+trow*4+i;
#pragma unroll
        for(int j=0;j<4;j++){
            int n=n0+tcol*4+j;
            g_outPart[((size_t)z*BB+m)*OUTT+n]=acc[i][j];
        }
    }
}
__global__ void k_reduce(const float* __restrict__ out_b, float* __restrict__ outp, int total)
{
    int idx = blockIdx.x*256 + threadIdx.x;
    if (idx >= total) return;
    if (idx < BB*OUTT){
        float s = out_b[idx & (OUTT-1)];
#pragma unroll
        for(int z=0;z<16;z++) s += g_outPart[(size_t)z*(BB*OUTT)+idx];
        outp[idx]=s;
    } else if (idx < BB*OUTT + VV*BB){
        outp[idx] = g_dists[idx - BB*OUTT];
    }
}

// ---------------- launch ----------------
extern "C" void kernel_launch(void* const* d_in, const int* in_sizes, int n_in,
                              void* d_out, int out_size)
{
    const int*   node_ids  = (const int*)d_in[0];
    const float* timev     = (const float*)d_in[3];
    const float* embed     = (const float*)d_in[6];
    const float* kernel_w  = (const float*)d_in[7];
    const float* kernel_b  = (const float*)d_in[8];
    const float* rec_w     = (const float*)d_in[9];
    const float* rec_b     = (const float*)d_in[10];
    const float* scale_w   = (const float*)d_in[11];
    const float* scale_b   = (const float*)d_in[12];
    const float* rescale_w = (const float*)d_in[13];
    const float* rescale_b = (const float*)d_in[14];
    const float* conv_w    = (const float*)d_in[15];
    const float* conv_b    = (const float*)d_in[16];
    const float* out_w     = (const float*)d_in[17];
    const float* out_b     = (const float*)d_in[18];
    float* outp = (float*)d_out;

    const int SMEM = 2*128*LDT*2*4;                       // 81920
    const int SMEM_R = (2*32*392 + 2*2*256*LDT)*2;        // 132096
    static bool cfg = false;
    if (!cfg){
        cudaFuncSetAttribute(k_gma<0>, cudaFuncAttributeMaxDynamicSharedMemorySize, SMEM);
        cudaFuncSetAttribute(k_gma<1>, cudaFuncAttributeMaxDynamicSharedMemorySize, SMEM);
        cudaFuncSetAttribute(k_recur, cudaFuncAttributeMaxDynamicSharedMemorySize, SMEM_R);
        cfg = true;
    }

    long prep_total = (long)GPAD*NDI + 10001L*DD + (long)HH*KC2 + GG + (long)GP2*HH + (long)BB*HH;
    k_prep<<<(int)((prep_total+255)/256), 256>>>(kernel_w, rec_w, conv_w, kernel_b, rec_b, embed);

    k_gma<0><<<dim3(13,100), 256, SMEM>>>(node_ids, timev, conv_b);
    k_recur<<<64, 256, SMEM_R>>>();
    k_ld<<<50, 256>>>();
    k_mh<<<19200, 256>>>();
    k_theme1<<<dim3(1,200), 256>>>(scale_w, scale_b);
    k_theme2<<<dim3(6,200), 256>>>(rescale_w, rescale_b);
    k_gma<1><<<dim3(3,100), 256, SMEM>>>(node_ids, timev, conv_b);
    k_out<<<dim3(2,4,16), 256>>>(out_w);
    k_reduce<<<(out_size+255)/256, 256>>>(out_b, outp, out_size);
}